// round 1
// baseline (speedup 1.0000x reference)
#include <cuda_runtime.h>
#include <cstddef>

#define NN   50000
#define DDIM 512
#define DOUT 128

// Scratch (device globals: allocation-free rule)
__device__ float g_agg[(size_t)NN * DDIM];
__device__ float g_h1 [(size_t)NN * DDIM];
__device__ float g_h2 [(size_t)NN * DDIM];
__device__ float g_deg[NN];

// ---------------------------------------------------------------------------
__global__ void zero4_kernel(float4* p, int n4) {
    int i = blockIdx.x * blockDim.x + threadIdx.x;
    int stride = gridDim.x * blockDim.x;
    float4 z = make_float4(0.f, 0.f, 0.f, 0.f);
    for (; i < n4; i += stride) p[i] = z;
}

__global__ void zero1_kernel(float* p, int n) {
    int i = blockIdx.x * blockDim.x + threadIdx.x;
    if (i < n) p[i] = 0.f;
}

__global__ void deg_kernel(const int* __restrict__ dst, float* __restrict__ deg, int E) {
    int e = blockIdx.x * blockDim.x + threadIdx.x;
    if (e < E) atomicAdd(&deg[dst[e]], 1.0f);
}

// One warp per edge: 512 floats = 4 float4 per lane, coalesced.
__global__ void scatter_add_kernel(const float* __restrict__ x,
                                   const int* __restrict__ src,
                                   const int* __restrict__ dst,
                                   float* __restrict__ agg, int E) {
    int warp = (blockIdx.x * blockDim.x + threadIdx.x) >> 5;
    int lane = threadIdx.x & 31;
    if (warp >= E) return;
    int s = src[warp];
    int d = dst[warp];
    const float4* xs = (const float4*)(x + (size_t)s * DDIM);
    float* a = agg + (size_t)d * DDIM;
#pragma unroll
    for (int i = 0; i < 4; i++) {
        int idx = lane + 32 * i;        // float4 index within row (0..127)
        float4 v = xs[idx];
        int base = idx * 4;
        atomicAdd(a + base + 0, v.x);
        atomicAdd(a + base + 1, v.y);
        atomicAdd(a + base + 2, v.z);
        atomicAdd(a + base + 3, v.w);
    }
}

// agg[row][*] /= max(deg[row],1)   (in-place, float4 granularity)
__global__ void mean_kernel(float4* __restrict__ agg, const float* __restrict__ deg, int n4) {
    int i = blockIdx.x * blockDim.x + threadIdx.x;
    int stride = gridDim.x * blockDim.x;
    for (; i < n4; i += stride) {
        int row = i >> 7;               // 128 float4 per 512-wide row
        float dg = deg[row];
        float sc = 1.0f / fmaxf(dg, 1.0f);
        float4 v = agg[i];
        v.x *= sc; v.y *= sc; v.z *= sc; v.w *= sc;
        agg[i] = v;
    }
}

// ---------------------------------------------------------------------------
// Fused GEMM: C[M,N] = A0[M,512] @ B0[512,N] + A1[M,512] @ B1[512,N] + bias
// (i.e. [A0|A1] @ [B0;B1], K = 1024). Optional ReLU.
// Tile: 64x64x16, 256 threads, 4x4 register block per thread.
template <bool RELU>
__global__ void gemm_fused_kernel(const float* __restrict__ A0,
                                  const float* __restrict__ A1,
                                  const float* __restrict__ B0,
                                  const float* __restrict__ B1,
                                  const float* __restrict__ bias,
                                  float* __restrict__ C, int M, int N) {
    __shared__ float As[16][64];
    __shared__ float Bs[16][64];

    const int tid   = threadIdx.x;
    const int mBase = blockIdx.y * 64;
    const int nBase = blockIdx.x * 64;

    // A tile load mapping: 64 rows x 16 k, float4 per thread
    const int la_row = tid >> 2;          // 0..63
    const int la_k   = (tid & 3) * 4;     // 0,4,8,12
    // B tile load mapping: 16 k x 64 n, float4 per thread
    const int lb_k   = tid >> 4;          // 0..15
    const int lb_n   = (tid & 15) * 4;    // 0..60
    // Compute mapping
    const int tr = (tid >> 4) * 4;        // m offset 0..60
    const int tc = (tid & 15) * 4;        // n offset 0..60

    const int  arow    = mBase + la_row;
    const bool arow_ok = (arow < M);

    float acc[4][4];
#pragma unroll
    for (int i = 0; i < 4; i++)
#pragma unroll
        for (int j = 0; j < 4; j++) acc[i][j] = 0.f;

    for (int kt = 0; kt < 64; kt++) {
        const float* Ah = (kt < 32) ? A0 : A1;
        const float* Bh = (kt < 32) ? B0 : B1;
        const int klocal = (kt & 31) * 16;

        float4 av = arow_ok
            ? *(const float4*)(Ah + (size_t)arow * DDIM + klocal + la_k)
            : make_float4(0.f, 0.f, 0.f, 0.f);
        As[la_k + 0][la_row] = av.x;
        As[la_k + 1][la_row] = av.y;
        As[la_k + 2][la_row] = av.z;
        As[la_k + 3][la_row] = av.w;

        float4 bv = *(const float4*)(Bh + (size_t)(klocal + lb_k) * N + nBase + lb_n);
        *(float4*)&Bs[lb_k][lb_n] = bv;

        __syncthreads();

#pragma unroll
        for (int kk = 0; kk < 16; kk++) {
            float4 a4 = *(const float4*)&As[kk][tr];
            float4 b4 = *(const float4*)&Bs[kk][tc];
            acc[0][0] += a4.x * b4.x; acc[0][1] += a4.x * b4.y;
            acc[0][2] += a4.x * b4.z; acc[0][3] += a4.x * b4.w;
            acc[1][0] += a4.y * b4.x; acc[1][1] += a4.y * b4.y;
            acc[1][2] += a4.y * b4.z; acc[1][3] += a4.y * b4.w;
            acc[2][0] += a4.z * b4.x; acc[2][1] += a4.z * b4.y;
            acc[2][2] += a4.z * b4.z; acc[2][3] += a4.z * b4.w;
            acc[3][0] += a4.w * b4.x; acc[3][1] += a4.w * b4.y;
            acc[3][2] += a4.w * b4.z; acc[3][3] += a4.w * b4.w;
        }
        __syncthreads();
    }

    // Epilogue: bias (+ ReLU), float4 stores
    float4 bsv = *(const float4*)(bias + nBase + tc);
#pragma unroll
    for (int i = 0; i < 4; i++) {
        int row = mBase + tr + i;
        if (row < M) {
            float4 r;
            r.x = acc[i][0] + bsv.x;
            r.y = acc[i][1] + bsv.y;
            r.z = acc[i][2] + bsv.z;
            r.w = acc[i][3] + bsv.w;
            if (RELU) {
                r.x = fmaxf(r.x, 0.f); r.y = fmaxf(r.y, 0.f);
                r.z = fmaxf(r.z, 0.f); r.w = fmaxf(r.w, 0.f);
            }
            *(float4*)(C + (size_t)row * N + nBase + tc) = r;
        }
    }
}

// In-place log_softmax over rows of 128, one warp per row.
__global__ void log_softmax128_kernel(float* __restrict__ out, int M) {
    int row  = blockIdx.x * (blockDim.x >> 5) + (threadIdx.x >> 5);
    int lane = threadIdx.x & 31;
    if (row >= M) return;
    float4* p = (float4*)(out + (size_t)row * DOUT);
    float4 v = p[lane];
    float mx = fmaxf(fmaxf(v.x, v.y), fmaxf(v.z, v.w));
#pragma unroll
    for (int o = 16; o; o >>= 1) mx = fmaxf(mx, __shfl_xor_sync(0xffffffffu, mx, o));
    float s = expf(v.x - mx) + expf(v.y - mx) + expf(v.z - mx) + expf(v.w - mx);
#pragma unroll
    for (int o = 16; o; o >>= 1) s += __shfl_xor_sync(0xffffffffu, s, o);
    float l = mx + logf(s);
    v.x -= l; v.y -= l; v.z -= l; v.w -= l;
    p[lane] = v;
}

// ---------------------------------------------------------------------------
extern "C" void kernel_launch(void* const* d_in, const int* in_sizes, int n_in,
                              void* d_out, int out_size) {
    const float* x   = (const float*)d_in[0];
    const int*   ei  = (const int*)  d_in[1];
    const float* W1l = (const float*)d_in[2];
    const float* b1  = (const float*)d_in[3];
    const float* W1r = (const float*)d_in[4];
    const float* W2l = (const float*)d_in[5];
    const float* b2  = (const float*)d_in[6];
    const float* W2r = (const float*)d_in[7];
    const float* W3l = (const float*)d_in[8];
    const float* b3  = (const float*)d_in[9];
    const float* W3r = (const float*)d_in[10];
    float* out = (float*)d_out;

    const int E = in_sizes[1] / 2;
    const int M = in_sizes[0] / DDIM;
    const int* src = ei;
    const int* dst = ei + E;

    float *agg, *h1, *h2, *deg;
    cudaGetSymbolAddress((void**)&agg, g_agg);
    cudaGetSymbolAddress((void**)&h1,  g_h1);
    cudaGetSymbolAddress((void**)&h2,  g_h2);
    cudaGetSymbolAddress((void**)&deg, g_deg);

    const int n4 = M * DDIM / 4;               // float4 count of a feature buffer
    const int scatterBlocks = (E * 32 + 255) / 256;

    // Degree (shared by all 3 layers)
    zero1_kernel<<<(M + 255) / 256, 256>>>(deg, M);
    deg_kernel<<<(E + 255) / 256, 256>>>(dst, deg, E);

    dim3 gemmGrid512(DDIM / 64, (M + 63) / 64);
    dim3 gemmGrid128(DOUT / 64, (M + 63) / 64);

    // ---- Layer 1 ----
    zero4_kernel<<<4096, 256>>>((float4*)agg, n4);
    scatter_add_kernel<<<scatterBlocks, 256>>>(x, src, dst, agg, E);
    mean_kernel<<<4096, 256>>>((float4*)agg, deg, n4);
    gemm_fused_kernel<true><<<gemmGrid512, 256>>>(agg, x, W1l, W1r, b1, h1, M, DDIM);

    // ---- Layer 2 ----
    zero4_kernel<<<4096, 256>>>((float4*)agg, n4);
    scatter_add_kernel<<<scatterBlocks, 256>>>(h1, src, dst, agg, E);
    mean_kernel<<<4096, 256>>>((float4*)agg, deg, n4);
    gemm_fused_kernel<true><<<gemmGrid512, 256>>>(agg, h1, W2l, W2r, b2, h2, M, DDIM);

    // ---- Layer 3 ----
    zero4_kernel<<<4096, 256>>>((float4*)agg, n4);
    scatter_add_kernel<<<scatterBlocks, 256>>>(h2, src, dst, agg, E);
    mean_kernel<<<4096, 256>>>((float4*)agg, deg, n4);
    gemm_fused_kernel<false><<<gemmGrid128, 256>>>(agg, h2, W3l, W3r, b3, out, M, DOUT);

    // log_softmax in place on d_out
    log_softmax128_kernel<<<(M + 7) / 8, 256>>>(out, M);
    (void)n_in; (void)out_size;
}

// round 2
// speedup vs baseline: 1.6287x; 1.6287x over previous
#include <cuda_runtime.h>
#include <cstddef>

#define NN   50000
#define EE   400000
#define DDIM 512
#define DOUT 128
#define SCAN_B 512

// Scratch (device globals: allocation-free rule)
__device__ float g_agg[(size_t)NN * DDIM];
__device__ float g_h1 [(size_t)NN * DDIM];
__device__ float g_h2 [(size_t)NN * DDIM];
__device__ int   g_deg[NN];
__device__ int   g_rowptr[NN + 1];
__device__ int   g_cursor[NN];
__device__ int   g_csr[EE];
__device__ int   g_bsums[(NN + SCAN_B - 1) / SCAN_B + 1];

// ---------------------------------------------------------------------------
// CSR construction
// ---------------------------------------------------------------------------
__global__ void zero_int_kernel(int* p, int n) {
    int i = blockIdx.x * blockDim.x + threadIdx.x;
    if (i < n) p[i] = 0;
}

__global__ void deg_kernel(const int* __restrict__ dst, int* __restrict__ deg, int E) {
    int e = blockIdx.x * blockDim.x + threadIdx.x;
    if (e < E) atomicAdd(&deg[dst[e]], 1);
}

// Per-chunk exclusive scan; chunk totals to bsums.
__global__ void scan1_kernel(const int* __restrict__ deg, int* __restrict__ rowptr,
                             int* __restrict__ bsums, int M) {
    __shared__ int sh[SCAN_B];
    int tid = threadIdx.x;
    int i = blockIdx.x * SCAN_B + tid;
    int v = (i < M) ? deg[i] : 0;
    sh[tid] = v;
    __syncthreads();
#pragma unroll
    for (int off = 1; off < SCAN_B; off <<= 1) {
        int t = (tid >= off) ? sh[tid - off] : 0;
        __syncthreads();
        sh[tid] += t;
        __syncthreads();
    }
    if (i < M) rowptr[i] = sh[tid] - v;   // exclusive within chunk
    if (tid == SCAN_B - 1) bsums[blockIdx.x] = sh[tid];
}

// Scan of chunk totals (tiny, single thread) + final rowptr[M].
__global__ void scan2_kernel(int* bsums, int* rowptr, int nblk, int M) {
    int run = 0;
    for (int b = 0; b < nblk; b++) { int t = bsums[b]; bsums[b] = run; run += t; }
    rowptr[M] = run;
}

__global__ void scan3_kernel(int* rowptr, const int* __restrict__ bsums, int M) {
    int i = blockIdx.x * blockDim.x + threadIdx.x;
    if (i < M) rowptr[i] += bsums[i / SCAN_B];
}

__global__ void csr_fill_kernel(const int* __restrict__ src, const int* __restrict__ dst,
                                const int* __restrict__ rowptr, int* __restrict__ cursor,
                                int* __restrict__ csr, int E) {
    int e = blockIdx.x * blockDim.x + threadIdx.x;
    if (e < E) {
        int d = dst[e];
        int pos = atomicAdd(&cursor[d], 1);
        csr[rowptr[d] + pos] = src[e];
    }
}

// ---------------------------------------------------------------------------
// Gather-mean: one block (128 thr) per node; agg[node] = mean of x[neighbors]
// ---------------------------------------------------------------------------
__global__ void gather_mean_kernel(const float* __restrict__ x,
                                   const int* __restrict__ rowptr,
                                   const int* __restrict__ csr,
                                   float* __restrict__ agg) {
    int node = blockIdx.x;
    int tid  = threadIdx.x;                 // 0..127, one float4 lane
    int beg = rowptr[node];
    int end = rowptr[node + 1];
    const float4* xb = (const float4*)x;
    float4 acc = make_float4(0.f, 0.f, 0.f, 0.f);
    int i = beg;
    // 2-deep software pipeline on independent neighbor rows
    for (; i + 1 < end; i += 2) {
        int s0 = csr[i], s1 = csr[i + 1];
        float4 v0 = xb[(size_t)s0 * 128 + tid];
        float4 v1 = xb[(size_t)s1 * 128 + tid];
        acc.x += v0.x + v1.x; acc.y += v0.y + v1.y;
        acc.z += v0.z + v1.z; acc.w += v0.w + v1.w;
    }
    if (i < end) {
        int s0 = csr[i];
        float4 v0 = xb[(size_t)s0 * 128 + tid];
        acc.x += v0.x; acc.y += v0.y; acc.z += v0.z; acc.w += v0.w;
    }
    float inv = 1.0f / (float)max(end - beg, 1);
    acc.x *= inv; acc.y *= inv; acc.z *= inv; acc.w *= inv;
    ((float4*)agg)[(size_t)node * 128 + tid] = acc;
}

// ---------------------------------------------------------------------------
// Fused GEMM: C[M,N] = A0 @ B0 + A1 @ B1 + bias  (K = 512 each half)
// Tile 128x128x16, 256 threads, 8x8 register block. Optional ReLU.
// ---------------------------------------------------------------------------
template <bool RELU>
__global__ __launch_bounds__(256, 2)
void gemm_fused_kernel(const float* __restrict__ A0,
                       const float* __restrict__ A1,
                       const float* __restrict__ B0,
                       const float* __restrict__ B1,
                       const float* __restrict__ bias,
                       float* __restrict__ C, int M, int N) {
    __shared__ float As[16][128];
    __shared__ float Bs[16][128];

    const int tid   = threadIdx.x;
    const int mBase = blockIdx.y * 128;
    const int nBase = blockIdx.x * 128;

    // A load: 128 rows x 16 k. Thread -> row tid&127, k-group (tid>>7)*8 (2 float4s)
    const int la_row = tid & 127;
    const int la_k   = (tid >> 7) * 8;
    // B load: 16 k-rows x 128 n. Thread -> k row tid>>4, col group (tid&15)*8 (2 float4s)
    const int lb_k = tid >> 4;
    const int lb_c = (tid & 15) * 8;
    // Compute mapping: 16x16 thread grid
    const int tx = tid & 15;   // n
    const int ty = tid >> 4;   // m

    const int  arow = mBase + la_row;
    const bool aok  = (arow < M);

    float acc[8][8];
#pragma unroll
    for (int i = 0; i < 8; i++)
#pragma unroll
        for (int j = 0; j < 8; j++) acc[i][j] = 0.f;

    for (int kt = 0; kt < 64; kt++) {
        const float* Ah = (kt < 32) ? A0 : A1;
        const float* Bh = (kt < 32) ? B0 : B1;
        const int kg = (kt & 31) * 16;

        float4 a0 = make_float4(0.f, 0.f, 0.f, 0.f), a1 = a0;
        if (aok) {
            const float* ap = Ah + (size_t)arow * DDIM + kg + la_k;
            a0 = *(const float4*)(ap);
            a1 = *(const float4*)(ap + 4);
        }
        const float* bp = Bh + (size_t)(kg + lb_k) * N + nBase + lb_c;
        float4 b0 = *(const float4*)(bp);
        float4 b1 = *(const float4*)(bp + 4);

        As[la_k + 0][la_row] = a0.x; As[la_k + 1][la_row] = a0.y;
        As[la_k + 2][la_row] = a0.z; As[la_k + 3][la_row] = a0.w;
        As[la_k + 4][la_row] = a1.x; As[la_k + 5][la_row] = a1.y;
        As[la_k + 6][la_row] = a1.z; As[la_k + 7][la_row] = a1.w;
        *(float4*)&Bs[lb_k][lb_c]     = b0;
        *(float4*)&Bs[lb_k][lb_c + 4] = b1;

        __syncthreads();

#pragma unroll
        for (int kk = 0; kk < 16; kk++) {
            float4 av0 = *(const float4*)&As[kk][ty * 4];
            float4 av1 = *(const float4*)&As[kk][ty * 4 + 64];
            float4 bv0 = *(const float4*)&Bs[kk][tx * 4];
            float4 bv1 = *(const float4*)&Bs[kk][tx * 4 + 64];
            float a[8] = {av0.x, av0.y, av0.z, av0.w, av1.x, av1.y, av1.z, av1.w};
            float b[8] = {bv0.x, bv0.y, bv0.z, bv0.w, bv1.x, bv1.y, bv1.z, bv1.w};
#pragma unroll
            for (int i = 0; i < 8; i++)
#pragma unroll
                for (int j = 0; j < 8; j++) acc[i][j] += a[i] * b[j];
        }
        __syncthreads();
    }

    // Epilogue
    float4 bias0 = *(const float4*)(bias + nBase + tx * 4);
    float4 bias1 = *(const float4*)(bias + nBase + tx * 4 + 64);
    float bb[8] = {bias0.x, bias0.y, bias0.z, bias0.w, bias1.x, bias1.y, bias1.z, bias1.w};
#pragma unroll
    for (int i = 0; i < 8; i++) {
        int row = mBase + ((i < 4) ? (ty * 4 + i) : (64 + ty * 4 + i - 4));
        if (row >= M) continue;
        float* cp = C + (size_t)row * N + nBase;
#pragma unroll
        for (int g = 0; g < 2; g++) {
            float4 r;
            r.x = acc[i][g * 4 + 0] + bb[g * 4 + 0];
            r.y = acc[i][g * 4 + 1] + bb[g * 4 + 1];
            r.z = acc[i][g * 4 + 2] + bb[g * 4 + 2];
            r.w = acc[i][g * 4 + 3] + bb[g * 4 + 3];
            if (RELU) {
                r.x = fmaxf(r.x, 0.f); r.y = fmaxf(r.y, 0.f);
                r.z = fmaxf(r.z, 0.f); r.w = fmaxf(r.w, 0.f);
            }
            *(float4*)(cp + tx * 4 + g * 64) = r;
        }
    }
}

// In-place log_softmax over rows of 128, one warp per row.
__global__ void log_softmax128_kernel(float* __restrict__ out, int M) {
    int row  = blockIdx.x * (blockDim.x >> 5) + (threadIdx.x >> 5);
    int lane = threadIdx.x & 31;
    if (row >= M) return;
    float4* p = (float4*)(out + (size_t)row * DOUT);
    float4 v = p[lane];
    float mx = fmaxf(fmaxf(v.x, v.y), fmaxf(v.z, v.w));
#pragma unroll
    for (int o = 16; o; o >>= 1) mx = fmaxf(mx, __shfl_xor_sync(0xffffffffu, mx, o));
    float s = expf(v.x - mx) + expf(v.y - mx) + expf(v.z - mx) + expf(v.w - mx);
#pragma unroll
    for (int o = 16; o; o >>= 1) s += __shfl_xor_sync(0xffffffffu, s, o);
    float l = mx + logf(s);
    v.x -= l; v.y -= l; v.z -= l; v.w -= l;
    p[lane] = v;
}

// ---------------------------------------------------------------------------
extern "C" void kernel_launch(void* const* d_in, const int* in_sizes, int n_in,
                              void* d_out, int out_size) {
    const float* x   = (const float*)d_in[0];
    const int*   ei  = (const int*)  d_in[1];
    const float* W1l = (const float*)d_in[2];
    const float* b1  = (const float*)d_in[3];
    const float* W1r = (const float*)d_in[4];
    const float* W2l = (const float*)d_in[5];
    const float* b2  = (const float*)d_in[6];
    const float* W2r = (const float*)d_in[7];
    const float* W3l = (const float*)d_in[8];
    const float* b3  = (const float*)d_in[9];
    const float* W3r = (const float*)d_in[10];
    float* out = (float*)d_out;

    const int E = in_sizes[1] / 2;
    const int M = in_sizes[0] / DDIM;
    const int* src = ei;
    const int* dst = ei + E;

    float *agg, *h1, *h2;
    int *deg, *rowptr, *cursor, *csr, *bsums;
    cudaGetSymbolAddress((void**)&agg,    g_agg);
    cudaGetSymbolAddress((void**)&h1,     g_h1);
    cudaGetSymbolAddress((void**)&h2,     g_h2);
    cudaGetSymbolAddress((void**)&deg,    g_deg);
    cudaGetSymbolAddress((void**)&rowptr, g_rowptr);
    cudaGetSymbolAddress((void**)&cursor, g_cursor);
    cudaGetSymbolAddress((void**)&csr,    g_csr);
    cudaGetSymbolAddress((void**)&bsums,  g_bsums);

    const int nblk = (M + SCAN_B - 1) / SCAN_B;

    // ---- CSR build (once; reused by all 3 layers) ----
    zero_int_kernel<<<(M + 255) / 256, 256>>>(deg, M);
    zero_int_kernel<<<(M + 255) / 256, 256>>>(cursor, M);
    deg_kernel<<<(E + 255) / 256, 256>>>(dst, deg, E);
    scan1_kernel<<<nblk, SCAN_B>>>(deg, rowptr, bsums, M);
    scan2_kernel<<<1, 1>>>(bsums, rowptr, nblk, M);
    scan3_kernel<<<(M + 255) / 256, 256>>>(rowptr, bsums, M);
    csr_fill_kernel<<<(E + 255) / 256, 256>>>(src, dst, rowptr, cursor, csr, E);

    dim3 gemmGrid512(DDIM / 128, (M + 127) / 128);
    dim3 gemmGrid128(DOUT / 128, (M + 127) / 128);

    // ---- Layer 1 ----
    gather_mean_kernel<<<M, 128>>>(x, rowptr, csr, agg);
    gemm_fused_kernel<true><<<gemmGrid512, 256>>>(agg, x, W1l, W1r, b1, h1, M, DDIM);

    // ---- Layer 2 ----
    gather_mean_kernel<<<M, 128>>>(h1, rowptr, csr, agg);
    gemm_fused_kernel<true><<<gemmGrid512, 256>>>(agg, h1, W2l, W2r, b2, h2, M, DDIM);

    // ---- Layer 3 ----
    gather_mean_kernel<<<M, 128>>>(h2, rowptr, csr, agg);
    gemm_fused_kernel<false><<<gemmGrid128, 256>>>(agg, h2, W3l, W3r, b3, out, M, DOUT);

    // log_softmax in place on d_out
    log_softmax128_kernel<<<(M + 7) / 8, 256>>>(out, M);
    (void)n_in; (void)out_size;
}

// round 6
// speedup vs baseline: 3.1013x; 1.9041x over previous
#include <cuda_runtime.h>
#include <cuda_bf16.h>
#include <cstdint>
#include <cstddef>

#define NN   50000
#define EE   400000
#define DDIM 512
#define DOUT 128
#define SCAN_B 512

// ---------------------------------------------------------------------------
// Scratch (device globals: allocation-free rule)
// Activations as planar bf16 hi/lo
__device__ __nv_bfloat16 g_xhi [(size_t)NN * DDIM];
__device__ __nv_bfloat16 g_xlo [(size_t)NN * DDIM];
__device__ __nv_bfloat16 g_ahi [(size_t)NN * DDIM];
__device__ __nv_bfloat16 g_alo [(size_t)NN * DDIM];
__device__ __nv_bfloat16 g_h1hi[(size_t)NN * DDIM];
__device__ __nv_bfloat16 g_h1lo[(size_t)NN * DDIM];
__device__ __nv_bfloat16 g_h2hi[(size_t)NN * DDIM];
__device__ __nv_bfloat16 g_h2lo[(size_t)NN * DDIM];
// Transposed weights [N][K] bf16 hi/lo
__device__ __nv_bfloat16 g_w1lhi[512*512], g_w1llo[512*512];
__device__ __nv_bfloat16 g_w1rhi[512*512], g_w1rlo[512*512];
__device__ __nv_bfloat16 g_w2lhi[512*512], g_w2llo[512*512];
__device__ __nv_bfloat16 g_w2rhi[512*512], g_w2rlo[512*512];
__device__ __nv_bfloat16 g_w3lhi[128*512], g_w3llo[128*512];
__device__ __nv_bfloat16 g_w3rhi[128*512], g_w3rlo[128*512];
// CSR
__device__ int g_deg[NN];
__device__ int g_rowptr[NN + 1];
__device__ int g_cursor[NN];
__device__ int g_csr[EE];
__device__ int g_bsums[(NN + SCAN_B - 1) / SCAN_B + 1];

// ---------------------------------------------------------------------------
// PTX helpers (base-arch only: ldmatrix / mma.sync / cp.async)
// ---------------------------------------------------------------------------
__device__ __forceinline__ uint32_t smem_to_u32(const void* p) {
    uint32_t a;
    asm("{ .reg .u64 t; cvta.to.shared.u64 t, %1; cvt.u32.u64 %0, t; }"
        : "=r"(a) : "l"(p));
    return a;
}

#define LDSM_X4(r0, r1, r2, r3, addr) \
    asm volatile("ldmatrix.sync.aligned.m8n8.x4.shared.b16 {%0,%1,%2,%3}, [%4];" \
        : "=r"(r0), "=r"(r1), "=r"(r2), "=r"(r3) : "r"(addr))

#define MMA_BF16(c, a, bv0, bv1) \
    asm volatile("mma.sync.aligned.m16n8k16.row.col.f32.bf16.bf16.f32 " \
        "{%0,%1,%2,%3}, {%4,%5,%6,%7}, {%8,%9}, {%0,%1,%2,%3};" \
        : "+f"((c)[0]), "+f"((c)[1]), "+f"((c)[2]), "+f"((c)[3]) \
        : "r"((a)[0]), "r"((a)[1]), "r"((a)[2]), "r"((a)[3]), "r"(bv0), "r"(bv1))

#define CP_ASYNC16(smem, gmem, sz) \
    asm volatile("cp.async.cg.shared.global [%0], [%1], 16, %2;" \
        :: "r"(smem), "l"(gmem), "r"(sz) : "memory")
#define CP_COMMIT() asm volatile("cp.async.commit_group;" ::: "memory")
#define CP_WAIT(n)  asm volatile("cp.async.wait_group %0;" :: "n"(n) : "memory")

// ---------------------------------------------------------------------------
// bf16 split helpers
// ---------------------------------------------------------------------------
__device__ __forceinline__ void split1(float v, float& hi, float& lo) {
    float h = __bfloat162float(__float2bfloat16(v));
    hi = h; lo = v - h;
}
__device__ __forceinline__ uint32_t pack_bf2(float a, float b) {
    __nv_bfloat162 t = __floats2bfloat162_rn(a, b);
    return *reinterpret_cast<uint32_t*>(&t);
}
__device__ __forceinline__ float2 unpack_bf2(uint32_t u) {
    __nv_bfloat162 t = *reinterpret_cast<__nv_bfloat162*>(&u);
    return __bfloat1622float2(t);
}

// ---------------------------------------------------------------------------
// CSR construction
// ---------------------------------------------------------------------------
__global__ void zero_int_kernel(int* p, int n) {
    int i = blockIdx.x * blockDim.x + threadIdx.x;
    if (i < n) p[i] = 0;
}
__global__ void deg_kernel(const int* __restrict__ dst, int* __restrict__ deg, int E) {
    int e = blockIdx.x * blockDim.x + threadIdx.x;
    if (e < E) atomicAdd(&deg[dst[e]], 1);
}
__global__ void scan1_kernel(const int* __restrict__ deg, int* __restrict__ rowptr,
                             int* __restrict__ bsums, int M) {
    __shared__ int sh[SCAN_B];
    int tid = threadIdx.x;
    int i = blockIdx.x * SCAN_B + tid;
    int v = (i < M) ? deg[i] : 0;
    sh[tid] = v;
    __syncthreads();
#pragma unroll
    for (int off = 1; off < SCAN_B; off <<= 1) {
        int t = (tid >= off) ? sh[tid - off] : 0;
        __syncthreads();
        sh[tid] += t;
        __syncthreads();
    }
    if (i < M) rowptr[i] = sh[tid] - v;
    if (tid == SCAN_B - 1) bsums[blockIdx.x] = sh[tid];
}
__global__ void scan2_kernel(int* bsums, int* rowptr, int nblk, int M) {
    int run = 0;
    for (int b = 0; b < nblk; b++) { int t = bsums[b]; bsums[b] = run; run += t; }
    rowptr[M] = run;
}
__global__ void scan3_kernel(int* rowptr, const int* __restrict__ bsums, int M) {
    int i = blockIdx.x * blockDim.x + threadIdx.x;
    if (i < M) rowptr[i] += bsums[i / SCAN_B];
}
__global__ void csr_fill_kernel(const int* __restrict__ src, const int* __restrict__ dst,
                                const int* __restrict__ rowptr, int* __restrict__ cursor,
                                int* __restrict__ csr, int E) {
    int e = blockIdx.x * blockDim.x + threadIdx.x;
    if (e < E) {
        int d = dst[e];
        int pos = atomicAdd(&cursor[d], 1);
        csr[rowptr[d] + pos] = src[e];
    }
}

// ---------------------------------------------------------------------------
// Conversions
// ---------------------------------------------------------------------------
__global__ void convx_kernel(const float4* __restrict__ x,
                             uint2* __restrict__ xhi, uint2* __restrict__ xlo, int n4) {
    int i = blockIdx.x * blockDim.x + threadIdx.x;
    int stride = gridDim.x * blockDim.x;
    for (; i < n4; i += stride) {
        float4 v = x[i];
        float h0,l0,h1,l1,h2,l2,h3,l3;
        split1(v.x,h0,l0); split1(v.y,h1,l1); split1(v.z,h2,l2); split1(v.w,h3,l3);
        uint2 uh, ul;
        uh.x = pack_bf2(h0,h1); uh.y = pack_bf2(h2,h3);
        ul.x = pack_bf2(l0,l1); ul.y = pack_bf2(l2,l3);
        xhi[i] = uh; xlo[i] = ul;
    }
}

// Transpose + split weights: W fp32 [K][N] -> Whi/Wlo bf16 [N][K]
__global__ void wconv_kernel(const float* __restrict__ W,
                             __nv_bfloat16* __restrict__ Whi,
                             __nv_bfloat16* __restrict__ Wlo, int K, int N) {
    __shared__ float t[32][33];
    int nb = blockIdx.x * 32, kb = blockIdx.y * 32;
    for (int i = threadIdx.y; i < 32; i += 8)
        t[i][threadIdx.x] = W[(size_t)(kb + i) * N + nb + threadIdx.x];
    __syncthreads();
    for (int i = threadIdx.y; i < 32; i += 8) {
        float v = t[threadIdx.x][i];
        float h, l; split1(v, h, l);
        size_t o = (size_t)(nb + i) * K + kb + threadIdx.x;
        Whi[o] = __float2bfloat16(h);
        Wlo[o] = __float2bfloat16(l);
    }
}

// ---------------------------------------------------------------------------
// Gather-mean on bf16 hi/lo: one block (128 thr) per node
// ---------------------------------------------------------------------------
__global__ void gather_mean_kernel(const __nv_bfloat16* __restrict__ xhi,
                                   const __nv_bfloat16* __restrict__ xlo,
                                   const int* __restrict__ rowptr,
                                   const int* __restrict__ csr,
                                   __nv_bfloat16* __restrict__ ahi,
                                   __nv_bfloat16* __restrict__ alo) {
    int node = blockIdx.x;
    int tid  = threadIdx.x;
    int beg = rowptr[node], end = rowptr[node + 1];
    const uint2* XH = (const uint2*)xhi;
    const uint2* XL = (const uint2*)xlo;
    float a0 = 0.f, a1 = 0.f, a2 = 0.f, a3 = 0.f;
    int i = beg;
    for (; i + 1 < end; i += 2) {
        int s0 = csr[i], s1 = csr[i + 1];
        uint2 h0 = XH[(size_t)s0 * 128 + tid], l0 = XL[(size_t)s0 * 128 + tid];
        uint2 h1 = XH[(size_t)s1 * 128 + tid], l1 = XL[(size_t)s1 * 128 + tid];
        float2 p, q;
        p = unpack_bf2(h0.x); q = unpack_bf2(l0.x); a0 += p.x + q.x; a1 += p.y + q.y;
        p = unpack_bf2(h0.y); q = unpack_bf2(l0.y); a2 += p.x + q.x; a3 += p.y + q.y;
        p = unpack_bf2(h1.x); q = unpack_bf2(l1.x); a0 += p.x + q.x; a1 += p.y + q.y;
        p = unpack_bf2(h1.y); q = unpack_bf2(l1.y); a2 += p.x + q.x; a3 += p.y + q.y;
    }
    if (i < end) {
        int s0 = csr[i];
        uint2 h0 = XH[(size_t)s0 * 128 + tid], l0 = XL[(size_t)s0 * 128 + tid];
        float2 p, q;
        p = unpack_bf2(h0.x); q = unpack_bf2(l0.x); a0 += p.x + q.x; a1 += p.y + q.y;
        p = unpack_bf2(h0.y); q = unpack_bf2(l0.y); a2 += p.x + q.x; a3 += p.y + q.y;
    }
    float inv = 1.0f / (float)max(end - beg, 1);
    a0 *= inv; a1 *= inv; a2 *= inv; a3 *= inv;
    float h0,l0,h1,l1,h2,l2,h3,l3;
    split1(a0,h0,l0); split1(a1,h1,l1); split1(a2,h2,l2); split1(a3,h3,l3);
    uint2 uh, ul;
    uh.x = pack_bf2(h0,h1); uh.y = pack_bf2(h2,h3);
    ul.x = pack_bf2(l0,l1); ul.y = pack_bf2(l2,l3);
    ((uint2*)ahi)[(size_t)node * 128 + tid] = uh;
    ((uint2*)alo)[(size_t)node * 128 + tid] = ul;
}

// ---------------------------------------------------------------------------
// mma.sync bf16-split GEMM:
// C[M, Ntot] = (A0hi+A0lo) @ B0^T + (A1hi+A1lo) @ B1^T + bias  (each K half 512)
// Products kept: AhiBhi + AhiBlo + AloBhi. fp32 register accumulators.
// CTA tile 128x128, 8 warps (4m x 2n), warp tile 32x64 (2 x 8 m16n8k16).
// SMEM: 2-stage cp.async pipeline, K-chunk 32 halves, row stride 80B
// (conflict-free for ldmatrix). A row-major [M][K], B row-major [N][K].
// ---------------------------------------------------------------------------
template <bool HILO_RELU>
__global__ __launch_bounds__(256)
void gemm_mma(const __nv_bfloat16* __restrict__ A0hi, const __nv_bfloat16* __restrict__ A0lo,
              const __nv_bfloat16* __restrict__ A1hi, const __nv_bfloat16* __restrict__ A1lo,
              const __nv_bfloat16* __restrict__ B0hi, const __nv_bfloat16* __restrict__ B0lo,
              const __nv_bfloat16* __restrict__ B1hi, const __nv_bfloat16* __restrict__ B1lo,
              const float* __restrict__ bias,
              float* __restrict__ Cf,
              __nv_bfloat16* __restrict__ Chi, __nv_bfloat16* __restrict__ Clo,
              int M, int Ntot) {
    extern __shared__ char dsm[];
    constexpr int SROW  = 80;          // bytes per 32-half row (padded from 64)
    constexpr int PLANE = 128 * SROW;  // 10240 B
    constexpr int STAGE = 4 * PLANE;   // 40960 B: Ahi, Alo, Bhi, Blo
    constexpr int OFF_AHI = 0, OFF_ALO = PLANE, OFF_BHI = 2*PLANE, OFF_BLO = 3*PLANE;

    const int tid  = threadIdx.x;
    const int wid  = tid >> 5;
    const int lane = tid & 31;
    const int wm = wid >> 1;           // 0..3 -> m offset wm*32
    const int wn = wid & 1;            // 0..1 -> n offset wn*64
    const int mBase = blockIdx.y * 128;
    const int nBase = blockIdx.x * 128;
    const uint32_t smem = smem_to_u32(dsm);

    // ---- async loader for one K-chunk (32 halves) into stage s ----
    auto issue_chunk = [&](int ch, int s) {
        const bool half = (ch >= 16);
        const char* Ah = (const char*)(half ? A1hi : A0hi);
        const char* Al = (const char*)(half ? A1lo : A0lo);
        const char* Bh = (const char*)(half ? B1hi : B0hi);
        const char* Bl = (const char*)(half ? B1lo : B0lo);
        const int k0b = (ch & 15) * 64;          // byte offset within 1024B row
        const uint32_t sb = smem + s * STAGE;
#pragma unroll
        for (int it = 0; it < 2; it++) {
            int c = tid + it * 256;              // 0..511
            int row = c >> 2, q = c & 3;
            uint32_t soff = row * SROW + q * 16;
            int am = mBase + row;
            int asz = (am < M) ? 16 : 0;
            size_t ga = (size_t)(am < M ? am : 0) * 1024 + k0b + q * 16;
            CP_ASYNC16(sb + OFF_AHI + soff, Ah + ga, asz);
            CP_ASYNC16(sb + OFF_ALO + soff, Al + ga, asz);
            size_t gb = (size_t)(nBase + row) * 1024 + k0b + q * 16;
            CP_ASYNC16(sb + OFF_BHI + soff, Bh + gb, 16);
            CP_ASYNC16(sb + OFF_BLO + soff, Bl + gb, 16);
        }
        CP_COMMIT();
    };

    float acc[2][8][4];
#pragma unroll
    for (int i = 0; i < 2; i++)
#pragma unroll
        for (int j = 0; j < 8; j++)
#pragma unroll
            for (int k = 0; k < 4; k++) acc[i][j][k] = 0.f;

    const int g = lane >> 3, r = lane & 7;

    issue_chunk(0, 0);
    for (int ch = 0; ch < 32; ch++) {
        const int s = ch & 1;
        if (ch + 1 < 32) { issue_chunk(ch + 1, s ^ 1); CP_WAIT(1); }
        else             { CP_WAIT(0); }
        __syncthreads();

        const uint32_t sAhi = smem + s * STAGE + OFF_AHI;
        const uint32_t sAlo = smem + s * STAGE + OFF_ALO;
        const uint32_t sBhi = smem + s * STAGE + OFF_BHI;
        const uint32_t sBlo = smem + s * STAGE + OFF_BLO;

#pragma unroll
        for (int ks = 0; ks < 2; ks++) {
            // A fragments (2 m-tiles x hi/lo)
            uint32_t ah[2][4], al[2][4];
#pragma unroll
            for (int mi = 0; mi < 2; mi++) {
                uint32_t arow = wm * 32 + mi * 16 + ((g & 1) << 3) + r;
                uint32_t aoff = arow * SROW + ks * 32 + (g >> 1) * 16;
                LDSM_X4(ah[mi][0], ah[mi][1], ah[mi][2], ah[mi][3], sAhi + aoff);
                LDSM_X4(al[mi][0], al[mi][1], al[mi][2], al[mi][3], sAlo + aoff);
            }
            // B: 4 x (x4 ldmatrix covers two n8-tiles), hi+lo
#pragma unroll
            for (int j = 0; j < 4; j++) {
                uint32_t brow = wn * 64 + j * 16 + ((g >> 1) << 3) + r;
                uint32_t boff = brow * SROW + ks * 32 + (g & 1) * 16;
                uint32_t bh0, bh1, bh2, bh3, bl0, bl1, bl2, bl3;
                LDSM_X4(bh0, bh1, bh2, bh3, sBhi + boff);
                LDSM_X4(bl0, bl1, bl2, bl3, sBlo + boff);
#pragma unroll
                for (int mi = 0; mi < 2; mi++) {
                    MMA_BF16(acc[mi][j*2+0], ah[mi], bh0, bh1);
                    MMA_BF16(acc[mi][j*2+0], ah[mi], bl0, bl1);
                    MMA_BF16(acc[mi][j*2+0], al[mi], bh0, bh1);
                    MMA_BF16(acc[mi][j*2+1], ah[mi], bh2, bh3);
                    MMA_BF16(acc[mi][j*2+1], ah[mi], bl2, bl3);
                    MMA_BF16(acc[mi][j*2+1], al[mi], bh2, bh3);
                }
            }
        }
        __syncthreads();   // protect stage s before it is rewritten
    }

    // ---- Epilogue ----
    const int qrow = lane >> 2, qcol = lane & 3;
#pragma unroll
    for (int mi = 0; mi < 2; mi++) {
#pragma unroll
        for (int ni = 0; ni < 8; ni++) {
            int row0 = mBase + wm * 32 + mi * 16 + qrow;
            int col  = nBase + wn * 64 + ni * 8 + qcol * 2;
            float2 bb = *(const float2*)(bias + col);
#pragma unroll
            for (int h = 0; h < 2; h++) {
                int row = row0 + h * 8;
                if (row >= M) continue;
                float v0 = acc[mi][ni][h*2+0] + bb.x;
                float v1 = acc[mi][ni][h*2+1] + bb.y;
                if (HILO_RELU) {
                    v0 = fmaxf(v0, 0.f); v1 = fmaxf(v1, 0.f);
                    float h0,l0,h1,l1;
                    split1(v0,h0,l0); split1(v1,h1,l1);
                    *(uint32_t*)(Chi + (size_t)row * Ntot + col) = pack_bf2(h0,h1);
                    *(uint32_t*)(Clo + (size_t)row * Ntot + col) = pack_bf2(l0,l1);
                } else {
                    float2 o; o.x = v0; o.y = v1;
                    *(float2*)(Cf + (size_t)row * Ntot + col) = o;
                }
            }
        }
    }
}

// ---------------------------------------------------------------------------
// In-place log_softmax over rows of 128, one warp per row.
// ---------------------------------------------------------------------------
__global__ void log_softmax128_kernel(float* __restrict__ out, int M) {
    int row  = blockIdx.x * (blockDim.x >> 5) + (threadIdx.x >> 5);
    int lane = threadIdx.x & 31;
    if (row >= M) return;
    float4* p = (float4*)(out + (size_t)row * DOUT);
    float4 v = p[lane];
    float mx = fmaxf(fmaxf(v.x, v.y), fmaxf(v.z, v.w));
#pragma unroll
    for (int o = 16; o; o >>= 1) mx = fmaxf(mx, __shfl_xor_sync(0xffffffffu, mx, o));
    float s = expf(v.x - mx) + expf(v.y - mx) + expf(v.z - mx) + expf(v.w - mx);
#pragma unroll
    for (int o = 16; o; o >>= 1) s += __shfl_xor_sync(0xffffffffu, s, o);
    float l = mx + logf(s);
    v.x -= l; v.y -= l; v.z -= l; v.w -= l;
    p[lane] = v;
}

// ---------------------------------------------------------------------------
extern "C" void kernel_launch(void* const* d_in, const int* in_sizes, int n_in,
                              void* d_out, int out_size) {
    const float* x   = (const float*)d_in[0];
    const int*   ei  = (const int*)  d_in[1];
    const float* W1l = (const float*)d_in[2];
    const float* b1  = (const float*)d_in[3];
    const float* W1r = (const float*)d_in[4];
    const float* W2l = (const float*)d_in[5];
    const float* b2  = (const float*)d_in[6];
    const float* W2r = (const float*)d_in[7];
    const float* W3l = (const float*)d_in[8];
    const float* b3  = (const float*)d_in[9];
    const float* W3r = (const float*)d_in[10];
    float* out = (float*)d_out;

    const int E = in_sizes[1] / 2;
    const int M = in_sizes[0] / DDIM;
    const int* src = ei;
    const int* dst = ei + E;

    __nv_bfloat16 *xhi,*xlo,*ahi,*alo,*h1hi,*h1lo,*h2hi,*h2lo;
    __nv_bfloat16 *w1lhi,*w1llo,*w1rhi,*w1rlo,*w2lhi,*w2llo,*w2rhi,*w2rlo;
    __nv_bfloat16 *w3lhi,*w3llo,*w3rhi,*w3rlo;
    int *deg,*rowptr,*cursor,*csr,*bsums;
    cudaGetSymbolAddress((void**)&xhi,  g_xhi);  cudaGetSymbolAddress((void**)&xlo,  g_xlo);
    cudaGetSymbolAddress((void**)&ahi,  g_ahi);  cudaGetSymbolAddress((void**)&alo,  g_alo);
    cudaGetSymbolAddress((void**)&h1hi, g_h1hi); cudaGetSymbolAddress((void**)&h1lo, g_h1lo);
    cudaGetSymbolAddress((void**)&h2hi, g_h2hi); cudaGetSymbolAddress((void**)&h2lo, g_h2lo);
    cudaGetSymbolAddress((void**)&w1lhi, g_w1lhi); cudaGetSymbolAddress((void**)&w1llo, g_w1llo);
    cudaGetSymbolAddress((void**)&w1rhi, g_w1rhi); cudaGetSymbolAddress((void**)&w1rlo, g_w1rlo);
    cudaGetSymbolAddress((void**)&w2lhi, g_w2lhi); cudaGetSymbolAddress((void**)&w2llo, g_w2llo);
    cudaGetSymbolAddress((void**)&w2rhi, g_w2rhi); cudaGetSymbolAddress((void**)&w2rlo, g_w2rlo);
    cudaGetSymbolAddress((void**)&w3lhi, g_w3lhi); cudaGetSymbolAddress((void**)&w3llo, g_w3llo);
    cudaGetSymbolAddress((void**)&w3rhi, g_w3rhi); cudaGetSymbolAddress((void**)&w3rlo, g_w3rlo);
    cudaGetSymbolAddress((void**)&deg,    g_deg);
    cudaGetSymbolAddress((void**)&rowptr, g_rowptr);
    cudaGetSymbolAddress((void**)&cursor, g_cursor);
    cudaGetSymbolAddress((void**)&csr,    g_csr);
    cudaGetSymbolAddress((void**)&bsums,  g_bsums);

    const int nblk = (M + SCAN_B - 1) / SCAN_B;

    const int SMEM_GEMM = 2 * 4 * 128 * 80;  // 81920 B
    cudaFuncSetAttribute(gemm_mma<true>,  cudaFuncAttributeMaxDynamicSharedMemorySize, SMEM_GEMM);
    cudaFuncSetAttribute(gemm_mma<false>, cudaFuncAttributeMaxDynamicSharedMemorySize, SMEM_GEMM);

    // ---- CSR build ----
    zero_int_kernel<<<(M + 255) / 256, 256>>>(deg, M);
    zero_int_kernel<<<(M + 255) / 256, 256>>>(cursor, M);
    deg_kernel<<<(E + 255) / 256, 256>>>(dst, deg, E);
    scan1_kernel<<<nblk, SCAN_B>>>(deg, rowptr, bsums, M);
    scan2_kernel<<<1, 1>>>(bsums, rowptr, nblk, M);
    scan3_kernel<<<(M + 255) / 256, 256>>>(rowptr, bsums, M);
    csr_fill_kernel<<<(E + 255) / 256, 256>>>(src, dst, rowptr, cursor, csr, E);

    // ---- Conversions ----
    convx_kernel<<<2048, 256>>>((const float4*)x, (uint2*)xhi, (uint2*)xlo, M * DDIM / 4);
    wconv_kernel<<<dim3(512/32, 512/32), dim3(32, 8)>>>(W1l, w1lhi, w1llo, 512, 512);
    wconv_kernel<<<dim3(512/32, 512/32), dim3(32, 8)>>>(W1r, w1rhi, w1rlo, 512, 512);
    wconv_kernel<<<dim3(512/32, 512/32), dim3(32, 8)>>>(W2l, w2lhi, w2llo, 512, 512);
    wconv_kernel<<<dim3(512/32, 512/32), dim3(32, 8)>>>(W2r, w2rhi, w2rlo, 512, 512);
    wconv_kernel<<<dim3(128/32, 512/32), dim3(32, 8)>>>(W3l, w3lhi, w3llo, 512, 128);
    wconv_kernel<<<dim3(128/32, 512/32), dim3(32, 8)>>>(W3r, w3rhi, w3rlo, 512, 128);

    const int mTiles = (M + 127) / 128;

    // ---- Layer 1 ----
    gather_mean_kernel<<<M, 128>>>(xhi, xlo, rowptr, csr, ahi, alo);
    gemm_mma<true><<<dim3(4, mTiles), 256, SMEM_GEMM>>>(
        ahi, alo, xhi, xlo, w1lhi, w1llo, w1rhi, w1rlo, b1,
        nullptr, h1hi, h1lo, M, DDIM);

    // ---- Layer 2 ----
    gather_mean_kernel<<<M, 128>>>(h1hi, h1lo, rowptr, csr, ahi, alo);
    gemm_mma<true><<<dim3(4, mTiles), 256, SMEM_GEMM>>>(
        ahi, alo, h1hi, h1lo, w2lhi, w2llo, w2rhi, w2rlo, b2,
        nullptr, h2hi, h2lo, M, DDIM);

    // ---- Layer 3 ----
    gather_mean_kernel<<<M, 128>>>(h2hi, h2lo, rowptr, csr, ahi, alo);
    gemm_mma<false><<<dim3(1, mTiles), 256, SMEM_GEMM>>>(
        ahi, alo, h2hi, h2lo, w3lhi, w3llo, w3rhi, w3rlo, b3,
        out, nullptr, nullptr, M, DOUT);

    // log_softmax in place on d_out
    log_softmax128_kernel<<<(M + 7) / 8, 256>>>(out, M);
    (void)n_in; (void)out_size;
}

// round 7
// speedup vs baseline: 3.6764x; 1.1855x over previous
#include <cuda_runtime.h>
#include <cuda_bf16.h>
#include <cstdint>
#include <cstddef>

#define NN   50000
#define EE   400000
#define DDIM 512
#define DOUT 128
#define SCAN_B 512

// ---------------------------------------------------------------------------
// Scratch (device globals: allocation-free rule)
__device__ __nv_bfloat16 g_xhi [(size_t)NN * DDIM];
__device__ __nv_bfloat16 g_xlo [(size_t)NN * DDIM];
__device__ __nv_bfloat16 g_ahi [(size_t)NN * DDIM];
__device__ __nv_bfloat16 g_alo [(size_t)NN * DDIM];
__device__ __nv_bfloat16 g_h1hi[(size_t)NN * DDIM];
__device__ __nv_bfloat16 g_h1lo[(size_t)NN * DDIM];
__device__ __nv_bfloat16 g_h2hi[(size_t)NN * DDIM];
__device__ __nv_bfloat16 g_h2lo[(size_t)NN * DDIM];
// Transposed weights [N][K] bf16 hi/lo
__device__ __nv_bfloat16 g_w1lhi[512*512], g_w1llo[512*512];
__device__ __nv_bfloat16 g_w1rhi[512*512], g_w1rlo[512*512];
__device__ __nv_bfloat16 g_w2lhi[512*512], g_w2llo[512*512];
__device__ __nv_bfloat16 g_w2rhi[512*512], g_w2rlo[512*512];
__device__ __nv_bfloat16 g_w3lhi[128*512], g_w3llo[128*512];
__device__ __nv_bfloat16 g_w3rhi[128*512], g_w3rlo[128*512];
// CSR
__device__ int g_deg[NN];
__device__ int g_rowptr[NN + 1];
__device__ int g_cursor[NN];
__device__ int g_csr[EE];
__device__ int g_bsums[(NN + SCAN_B - 1) / SCAN_B + 1];

// ---------------------------------------------------------------------------
// PTX helpers (base-arch only: ldmatrix / mma.sync / cp.async)
// ---------------------------------------------------------------------------
__device__ __forceinline__ uint32_t smem_to_u32(const void* p) {
    uint32_t a;
    asm("{ .reg .u64 t; cvta.to.shared.u64 t, %1; cvt.u32.u64 %0, t; }"
        : "=r"(a) : "l"(p));
    return a;
}

#define LDSM_X4(r0, r1, r2, r3, addr) \
    asm volatile("ldmatrix.sync.aligned.m8n8.x4.shared.b16 {%0,%1,%2,%3}, [%4];" \
        : "=r"(r0), "=r"(r1), "=r"(r2), "=r"(r3) : "r"(addr))

#define MMA_BF16(c, a, bv0, bv1) \
    asm volatile("mma.sync.aligned.m16n8k16.row.col.f32.bf16.bf16.f32 " \
        "{%0,%1,%2,%3}, {%4,%5,%6,%7}, {%8,%9}, {%0,%1,%2,%3};" \
        : "+f"((c)[0]), "+f"((c)[1]), "+f"((c)[2]), "+f"((c)[3]) \
        : "r"((a)[0]), "r"((a)[1]), "r"((a)[2]), "r"((a)[3]), "r"(bv0), "r"(bv1))

#define CP_ASYNC16(smem, gmem, sz) \
    asm volatile("cp.async.cg.shared.global [%0], [%1], 16, %2;" \
        :: "r"(smem), "l"(gmem), "r"(sz) : "memory")
#define CP_COMMIT() asm volatile("cp.async.commit_group;" ::: "memory")
#define CP_WAIT(n)  asm volatile("cp.async.wait_group %0;" :: "n"(n) : "memory")

// ---------------------------------------------------------------------------
// bf16 split helpers
// ---------------------------------------------------------------------------
__device__ __forceinline__ void split1(float v, float& hi, float& lo) {
    float h = __bfloat162float(__float2bfloat16(v));
    hi = h; lo = v - h;
}
__device__ __forceinline__ uint32_t pack_bf2(float a, float b) {
    __nv_bfloat162 t = __floats2bfloat162_rn(a, b);
    return *reinterpret_cast<uint32_t*>(&t);
}
__device__ __forceinline__ float2 unpack_bf2(uint32_t u) {
    __nv_bfloat162 t = *reinterpret_cast<__nv_bfloat162*>(&u);
    return __bfloat1622float2(t);
}

// ---------------------------------------------------------------------------
// CSR construction
// ---------------------------------------------------------------------------
__global__ void zero_int_kernel(int* p, int n) {
    int i = blockIdx.x * blockDim.x + threadIdx.x;
    if (i < n) p[i] = 0;
}
__global__ void deg_kernel(const int* __restrict__ dst, int* __restrict__ deg, int E) {
    int e = blockIdx.x * blockDim.x + threadIdx.x;
    if (e < E) atomicAdd(&deg[dst[e]], 1);
}
__global__ void scan1_kernel(const int* __restrict__ deg, int* __restrict__ rowptr,
                             int* __restrict__ bsums, int M) {
    __shared__ int sh[SCAN_B];
    int tid = threadIdx.x;
    int i = blockIdx.x * SCAN_B + tid;
    int v = (i < M) ? deg[i] : 0;
    sh[tid] = v;
    __syncthreads();
#pragma unroll
    for (int off = 1; off < SCAN_B; off <<= 1) {
        int t = (tid >= off) ? sh[tid - off] : 0;
        __syncthreads();
        sh[tid] += t;
        __syncthreads();
    }
    if (i < M) rowptr[i] = sh[tid] - v;
    if (tid == SCAN_B - 1) bsums[blockIdx.x] = sh[tid];
}
__global__ void scan2_kernel(int* bsums, int* rowptr, int nblk, int M) {
    int run = 0;
    for (int b = 0; b < nblk; b++) { int t = bsums[b]; bsums[b] = run; run += t; }
    rowptr[M] = run;
}
__global__ void scan3_kernel(int* rowptr, const int* __restrict__ bsums, int M) {
    int i = blockIdx.x * blockDim.x + threadIdx.x;
    if (i < M) rowptr[i] += bsums[i / SCAN_B];
}
__global__ void csr_fill_kernel(const int* __restrict__ src, const int* __restrict__ dst,
                                const int* __restrict__ rowptr, int* __restrict__ cursor,
                                int* __restrict__ csr, int E) {
    int e = blockIdx.x * blockDim.x + threadIdx.x;
    if (e < E) {
        int d = dst[e];
        int pos = atomicAdd(&cursor[d], 1);
        csr[rowptr[d] + pos] = src[e];
    }
}

// ---------------------------------------------------------------------------
// Conversions
// ---------------------------------------------------------------------------
__global__ void convx_kernel(const float4* __restrict__ x,
                             uint2* __restrict__ xhi, uint2* __restrict__ xlo, int n4) {
    int i = blockIdx.x * blockDim.x + threadIdx.x;
    int stride = gridDim.x * blockDim.x;
    for (; i < n4; i += stride) {
        float4 v = x[i];
        float h0,l0,h1,l1,h2,l2,h3,l3;
        split1(v.x,h0,l0); split1(v.y,h1,l1); split1(v.z,h2,l2); split1(v.w,h3,l3);
        uint2 uh, ul;
        uh.x = pack_bf2(h0,h1); uh.y = pack_bf2(h2,h3);
        ul.x = pack_bf2(l0,l1); ul.y = pack_bf2(l2,l3);
        xhi[i] = uh; xlo[i] = ul;
    }
}

// Transpose + split weights: W fp32 [K][N] -> Whi/Wlo bf16 [N][K]
__global__ void wconv_kernel(const float* __restrict__ W,
                             __nv_bfloat16* __restrict__ Whi,
                             __nv_bfloat16* __restrict__ Wlo, int K, int N) {
    __shared__ float t[32][33];
    int nb = blockIdx.x * 32, kb = blockIdx.y * 32;
    for (int i = threadIdx.y; i < 32; i += 8)
        t[i][threadIdx.x] = W[(size_t)(kb + i) * N + nb + threadIdx.x];
    __syncthreads();
    for (int i = threadIdx.y; i < 32; i += 8) {
        float v = t[threadIdx.x][i];
        float h, l; split1(v, h, l);
        size_t o = (size_t)(nb + i) * K + kb + threadIdx.x;
        Whi[o] = __float2bfloat16(h);
        Wlo[o] = __float2bfloat16(l);
    }
}

// ---------------------------------------------------------------------------
// Gather-mean on bf16 hi/lo: 4 nodes per block, 64 threads (2 warps) per node,
// uint4 (8 bf16) per thread per plane.
// ---------------------------------------------------------------------------
__global__ void gather_mean_kernel(const __nv_bfloat16* __restrict__ xhi,
                                   const __nv_bfloat16* __restrict__ xlo,
                                   const int* __restrict__ rowptr,
                                   const int* __restrict__ csr,
                                   __nv_bfloat16* __restrict__ ahi,
                                   __nv_bfloat16* __restrict__ alo, int M) {
    int node = blockIdx.x * 4 + (threadIdx.x >> 6);
    int t    = threadIdx.x & 63;
    if (node >= M) return;
    int beg = rowptr[node], end = rowptr[node + 1];
    const uint4* XH = (const uint4*)xhi;
    const uint4* XL = (const uint4*)xlo;
    float a[8];
#pragma unroll
    for (int j = 0; j < 8; j++) a[j] = 0.f;

    auto accum = [&](uint4 u) {
        float2 p;
        p = unpack_bf2(u.x); a[0] += p.x; a[1] += p.y;
        p = unpack_bf2(u.y); a[2] += p.x; a[3] += p.y;
        p = unpack_bf2(u.z); a[4] += p.x; a[5] += p.y;
        p = unpack_bf2(u.w); a[6] += p.x; a[7] += p.y;
    };

    int i = beg;
    for (; i + 1 < end; i += 2) {
        int s0 = csr[i], s1 = csr[i + 1];
        uint4 h0 = XH[(size_t)s0 * 64 + t];
        uint4 l0 = XL[(size_t)s0 * 64 + t];
        uint4 h1 = XH[(size_t)s1 * 64 + t];
        uint4 l1 = XL[(size_t)s1 * 64 + t];
        accum(h0); accum(l0); accum(h1); accum(l1);
    }
    if (i < end) {
        int s0 = csr[i];
        accum(XH[(size_t)s0 * 64 + t]);
        accum(XL[(size_t)s0 * 64 + t]);
    }

    float inv = 1.0f / (float)max(end - beg, 1);
    uint4 uh, ul;
    uint32_t* ph = (uint32_t*)&uh;
    uint32_t* pl = (uint32_t*)&ul;
#pragma unroll
    for (int j = 0; j < 4; j++) {
        float v0 = a[j*2+0] * inv, v1 = a[j*2+1] * inv;
        float h0,l0,h1,l1;
        split1(v0,h0,l0); split1(v1,h1,l1);
        ph[j] = pack_bf2(h0,h1);
        pl[j] = pack_bf2(l0,l1);
    }
    ((uint4*)ahi)[(size_t)node * 64 + t] = uh;
    ((uint4*)alo)[(size_t)node * 64 + t] = ul;
}

// ---------------------------------------------------------------------------
// mma.sync bf16-split GEMM:
// C[M, Ntot] = (A0hi+A0lo) @ B0^T + (A1hi+A1lo) @ B1^T + bias  (each K half 512)
// Products kept: AhiBhi + AhiBlo + AloBhi. fp32 register accumulators.
// CTA tile 128x128, 8 warps (4m x 2n), warp tile 32x64 (2 x 8 m16n8k16).
// K-chunk 64 halves, 2-stage cp.async pipeline, ONE __syncthreads per chunk.
// SMEM row stride 144B (128B data + 16 pad): ldmatrix conflict-free.
// MMA issue order: product-major within each j so dependent MMAs on the same
// accumulator are separated by 4 independent MMAs (hides HMMA latency).
// ---------------------------------------------------------------------------
template <bool HILO_RELU>
__global__ __launch_bounds__(256)
void gemm_mma(const __nv_bfloat16* __restrict__ A0hi, const __nv_bfloat16* __restrict__ A0lo,
              const __nv_bfloat16* __restrict__ A1hi, const __nv_bfloat16* __restrict__ A1lo,
              const __nv_bfloat16* __restrict__ B0hi, const __nv_bfloat16* __restrict__ B0lo,
              const __nv_bfloat16* __restrict__ B1hi, const __nv_bfloat16* __restrict__ B1lo,
              const float* __restrict__ bias,
              float* __restrict__ Cf,
              __nv_bfloat16* __restrict__ Chi, __nv_bfloat16* __restrict__ Clo,
              int M, int Ntot) {
    extern __shared__ char dsm[];
    constexpr int SROW  = 144;         // 64 halves = 128B data + 16B pad
    constexpr int PLANE = 128 * SROW;  // 18432 B
    constexpr int STAGE = 4 * PLANE;   // 73728 B: Ahi, Alo, Bhi, Blo
    constexpr int OFF_AHI = 0, OFF_ALO = PLANE, OFF_BHI = 2*PLANE, OFF_BLO = 3*PLANE;

    const int tid  = threadIdx.x;
    const int wid  = tid >> 5;
    const int lane = tid & 31;
    const int wm = wid >> 1;
    const int wn = wid & 1;
    const int mBase = blockIdx.y * 128;
    const int nBase = blockIdx.x * 128;
    const uint32_t smem = smem_to_u32(dsm);

    // ---- async loader for one K-chunk (64 halves = 128B/row) into stage s ----
    auto issue_chunk = [&](int ch, int s) {
        const bool half = (ch >= 8);
        const char* Ah = (const char*)(half ? A1hi : A0hi);
        const char* Al = (const char*)(half ? A1lo : A0lo);
        const char* Bh = (const char*)(half ? B1hi : B0hi);
        const char* Bl = (const char*)(half ? B1lo : B0lo);
        const int k0b = (ch & 7) * 128;          // byte offset within 1024B row
        const uint32_t sb = smem + s * STAGE;
#pragma unroll
        for (int it = 0; it < 4; it++) {
            int c = tid + it * 256;              // 0..1023
            int row = c >> 3, q = c & 7;
            uint32_t soff = row * SROW + q * 16;
            int am = mBase + row;
            int asz = (am < M) ? 16 : 0;
            size_t ga = (size_t)(am < M ? am : 0) * 1024 + k0b + q * 16;
            CP_ASYNC16(sb + OFF_AHI + soff, Ah + ga, asz);
            CP_ASYNC16(sb + OFF_ALO + soff, Al + ga, asz);
            size_t gb = (size_t)(nBase + row) * 1024 + k0b + q * 16;
            CP_ASYNC16(sb + OFF_BHI + soff, Bh + gb, 16);
            CP_ASYNC16(sb + OFF_BLO + soff, Bl + gb, 16);
        }
        CP_COMMIT();
    };

    float acc[2][8][4];
#pragma unroll
    for (int i = 0; i < 2; i++)
#pragma unroll
        for (int j = 0; j < 8; j++)
#pragma unroll
            for (int k = 0; k < 4; k++) acc[i][j][k] = 0.f;

    const int g = lane >> 3, r = lane & 7;

    issue_chunk(0, 0);
    for (int ch = 0; ch < 16; ch++) {
        const int s = ch & 1;
        CP_WAIT(0);
        __syncthreads();                 // stage s data visible; stage s^1 free
        if (ch + 1 < 16) issue_chunk(ch + 1, s ^ 1);

        const uint32_t sAhi = smem + s * STAGE + OFF_AHI;
        const uint32_t sAlo = smem + s * STAGE + OFF_ALO;
        const uint32_t sBhi = smem + s * STAGE + OFF_BHI;
        const uint32_t sBlo = smem + s * STAGE + OFF_BLO;

#pragma unroll
        for (int ks = 0; ks < 4; ks++) {
            uint32_t ah[2][4], al[2][4];
#pragma unroll
            for (int mi = 0; mi < 2; mi++) {
                uint32_t arow = wm * 32 + mi * 16 + ((g & 1) << 3) + r;
                uint32_t aoff = arow * SROW + ks * 32 + (g >> 1) * 16;
                LDSM_X4(ah[mi][0], ah[mi][1], ah[mi][2], ah[mi][3], sAhi + aoff);
                LDSM_X4(al[mi][0], al[mi][1], al[mi][2], al[mi][3], sAlo + aoff);
            }
#pragma unroll
            for (int j = 0; j < 4; j++) {
                uint32_t brow = wn * 64 + j * 16 + ((g >> 1) << 3) + r;
                uint32_t boff = brow * SROW + ks * 32 + (g & 1) * 16;
                uint32_t bh0, bh1, bh2, bh3, bl0, bl1, bl2, bl3;
                LDSM_X4(bh0, bh1, bh2, bh3, sBhi + boff);
                LDSM_X4(bl0, bl1, bl2, bl3, sBlo + boff);
                // product-major order: each acc touched every 4th MMA
                MMA_BF16(acc[0][j*2+0], ah[0], bh0, bh1);
                MMA_BF16(acc[0][j*2+1], ah[0], bh2, bh3);
                MMA_BF16(acc[1][j*2+0], ah[1], bh0, bh1);
                MMA_BF16(acc[1][j*2+1], ah[1], bh2, bh3);

                MMA_BF16(acc[0][j*2+0], ah[0], bl0, bl1);
                MMA_BF16(acc[0][j*2+1], ah[0], bl2, bl3);
                MMA_BF16(acc[1][j*2+0], ah[1], bl0, bl1);
                MMA_BF16(acc[1][j*2+1], ah[1], bl2, bl3);

                MMA_BF16(acc[0][j*2+0], al[0], bh0, bh1);
                MMA_BF16(acc[0][j*2+1], al[0], bh2, bh3);
                MMA_BF16(acc[1][j*2+0], al[1], bh0, bh1);
                MMA_BF16(acc[1][j*2+1], al[1], bh2, bh3);
            }
        }
    }

    // ---- Epilogue ----
    const int qrow = lane >> 2, qcol = lane & 3;
#pragma unroll
    for (int mi = 0; mi < 2; mi++) {
#pragma unroll
        for (int ni = 0; ni < 8; ni++) {
            int row0 = mBase + wm * 32 + mi * 16 + qrow;
            int col  = nBase + wn * 64 + ni * 8 + qcol * 2;
            float2 bb = *(const float2*)(bias + col);
#pragma unroll
            for (int h = 0; h < 2; h++) {
                int row = row0 + h * 8;
                if (row >= M) continue;
                float v0 = acc[mi][ni][h*2+0] + bb.x;
                float v1 = acc[mi][ni][h*2+1] + bb.y;
                if (HILO_RELU) {
                    v0 = fmaxf(v0, 0.f); v1 = fmaxf(v1, 0.f);
                    float h0,l0,h1,l1;
                    split1(v0,h0,l0); split1(v1,h1,l1);
                    *(uint32_t*)(Chi + (size_t)row * Ntot + col) = pack_bf2(h0,h1);
                    *(uint32_t*)(Clo + (size_t)row * Ntot + col) = pack_bf2(l0,l1);
                } else {
                    float2 o; o.x = v0; o.y = v1;
                    *(float2*)(Cf + (size_t)row * Ntot + col) = o;
                }
            }
        }
    }
}

// ---------------------------------------------------------------------------
// In-place log_softmax over rows of 128, one warp per row.
// ---------------------------------------------------------------------------
__global__ void log_softmax128_kernel(float* __restrict__ out, int M) {
    int row  = blockIdx.x * (blockDim.x >> 5) + (threadIdx.x >> 5);
    int lane = threadIdx.x & 31;
    if (row >= M) return;
    float4* p = (float4*)(out + (size_t)row * DOUT);
    float4 v = p[lane];
    float mx = fmaxf(fmaxf(v.x, v.y), fmaxf(v.z, v.w));
#pragma unroll
    for (int o = 16; o; o >>= 1) mx = fmaxf(mx, __shfl_xor_sync(0xffffffffu, mx, o));
    float s = expf(v.x - mx) + expf(v.y - mx) + expf(v.z - mx) + expf(v.w - mx);
#pragma unroll
    for (int o = 16; o; o >>= 1) s += __shfl_xor_sync(0xffffffffu, s, o);
    float l = mx + logf(s);
    v.x -= l; v.y -= l; v.z -= l; v.w -= l;
    p[lane] = v;
}

// ---------------------------------------------------------------------------
extern "C" void kernel_launch(void* const* d_in, const int* in_sizes, int n_in,
                              void* d_out, int out_size) {
    const float* x   = (const float*)d_in[0];
    const int*   ei  = (const int*)  d_in[1];
    const float* W1l = (const float*)d_in[2];
    const float* b1  = (const float*)d_in[3];
    const float* W1r = (const float*)d_in[4];
    const float* W2l = (const float*)d_in[5];
    const float* b2  = (const float*)d_in[6];
    const float* W2r = (const float*)d_in[7];
    const float* W3l = (const float*)d_in[8];
    const float* b3  = (const float*)d_in[9];
    const float* W3r = (const float*)d_in[10];
    float* out = (float*)d_out;

    const int E = in_sizes[1] / 2;
    const int M = in_sizes[0] / DDIM;
    const int* src = ei;
    const int* dst = ei + E;

    __nv_bfloat16 *xhi,*xlo,*ahi,*alo,*h1hi,*h1lo,*h2hi,*h2lo;
    __nv_bfloat16 *w1lhi,*w1llo,*w1rhi,*w1rlo,*w2lhi,*w2llo,*w2rhi,*w2rlo;
    __nv_bfloat16 *w3lhi,*w3llo,*w3rhi,*w3rlo;
    int *deg,*rowptr,*cursor,*csr,*bsums;
    cudaGetSymbolAddress((void**)&xhi,  g_xhi);  cudaGetSymbolAddress((void**)&xlo,  g_xlo);
    cudaGetSymbolAddress((void**)&ahi,  g_ahi);  cudaGetSymbolAddress((void**)&alo,  g_alo);
    cudaGetSymbolAddress((void**)&h1hi, g_h1hi); cudaGetSymbolAddress((void**)&h1lo, g_h1lo);
    cudaGetSymbolAddress((void**)&h2hi, g_h2hi); cudaGetSymbolAddress((void**)&h2lo, g_h2lo);
    cudaGetSymbolAddress((void**)&w1lhi, g_w1lhi); cudaGetSymbolAddress((void**)&w1llo, g_w1llo);
    cudaGetSymbolAddress((void**)&w1rhi, g_w1rhi); cudaGetSymbolAddress((void**)&w1rlo, g_w1rlo);
    cudaGetSymbolAddress((void**)&w2lhi, g_w2lhi); cudaGetSymbolAddress((void**)&w2llo, g_w2llo);
    cudaGetSymbolAddress((void**)&w2rhi, g_w2rhi); cudaGetSymbolAddress((void**)&w2rlo, g_w2rlo);
    cudaGetSymbolAddress((void**)&w3lhi, g_w3lhi); cudaGetSymbolAddress((void**)&w3llo, g_w3llo);
    cudaGetSymbolAddress((void**)&w3rhi, g_w3rhi); cudaGetSymbolAddress((void**)&w3rlo, g_w3rlo);
    cudaGetSymbolAddress((void**)&deg,    g_deg);
    cudaGetSymbolAddress((void**)&rowptr, g_rowptr);
    cudaGetSymbolAddress((void**)&cursor, g_cursor);
    cudaGetSymbolAddress((void**)&csr,    g_csr);
    cudaGetSymbolAddress((void**)&bsums,  g_bsums);

    const int nblk = (M + SCAN_B - 1) / SCAN_B;

    const int SMEM_GEMM = 2 * 4 * 128 * 144;  // 147456 B
    cudaFuncSetAttribute(gemm_mma<true>,  cudaFuncAttributeMaxDynamicSharedMemorySize, SMEM_GEMM);
    cudaFuncSetAttribute(gemm_mma<false>, cudaFuncAttributeMaxDynamicSharedMemorySize, SMEM_GEMM);

    // ---- CSR build ----
    zero_int_kernel<<<(M + 255) / 256, 256>>>(deg, M);
    zero_int_kernel<<<(M + 255) / 256, 256>>>(cursor, M);
    deg_kernel<<<(E + 255) / 256, 256>>>(dst, deg, E);
    scan1_kernel<<<nblk, SCAN_B>>>(deg, rowptr, bsums, M);
    scan2_kernel<<<1, 1>>>(bsums, rowptr, nblk, M);
    scan3_kernel<<<(M + 255) / 256, 256>>>(rowptr, bsums, M);
    csr_fill_kernel<<<(E + 255) / 256, 256>>>(src, dst, rowptr, cursor, csr, E);

    // ---- Conversions ----
    convx_kernel<<<2048, 256>>>((const float4*)x, (uint2*)xhi, (uint2*)xlo, M * DDIM / 4);
    wconv_kernel<<<dim3(512/32, 512/32), dim3(32, 8)>>>(W1l, w1lhi, w1llo, 512, 512);
    wconv_kernel<<<dim3(512/32, 512/32), dim3(32, 8)>>>(W1r, w1rhi, w1rlo, 512, 512);
    wconv_kernel<<<dim3(512/32, 512/32), dim3(32, 8)>>>(W2l, w2lhi, w2llo, 512, 512);
    wconv_kernel<<<dim3(512/32, 512/32), dim3(32, 8)>>>(W2r, w2rhi, w2rlo, 512, 512);
    wconv_kernel<<<dim3(128/32, 512/32), dim3(32, 8)>>>(W3l, w3lhi, w3llo, 512, 128);
    wconv_kernel<<<dim3(128/32, 512/32), dim3(32, 8)>>>(W3r, w3rhi, w3rlo, 512, 128);

    const int mTiles = (M + 127) / 128;
    const int gBlocks = (M + 3) / 4;

    // ---- Layer 1 ----
    gather_mean_kernel<<<gBlocks, 256>>>(xhi, xlo, rowptr, csr, ahi, alo, M);
    gemm_mma<true><<<dim3(4, mTiles), 256, SMEM_GEMM>>>(
        ahi, alo, xhi, xlo, w1lhi, w1llo, w1rhi, w1rlo, b1,
        nullptr, h1hi, h1lo, M, DDIM);

    // ---- Layer 2 ----
    gather_mean_kernel<<<gBlocks, 256>>>(h1hi, h1lo, rowptr, csr, ahi, alo, M);
    gemm_mma<true><<<dim3(4, mTiles), 256, SMEM_GEMM>>>(
        ahi, alo, h1hi, h1lo, w2lhi, w2llo, w2rhi, w2rlo, b2,
        nullptr, h2hi, h2lo, M, DDIM);

    // ---- Layer 3 ----
    gather_mean_kernel<<<gBlocks, 256>>>(h2hi, h2lo, rowptr, csr, ahi, alo, M);
    gemm_mma<false><<<dim3(1, mTiles), 256, SMEM_GEMM>>>(
        ahi, alo, h2hi, h2lo, w3lhi, w3llo, w3rhi, w3rlo, b3,
        out, nullptr, nullptr, M, DOUT);

    // log_softmax in place on d_out
    log_softmax128_kernel<<<(M + 7) / 8, 256>>>(out, M);
    (void)n_in; (void)out_size;
}

// round 8
// speedup vs baseline: 4.1698x; 1.1342x over previous
#include <cuda_runtime.h>
#include <cuda_fp16.h>
#include <cstdint>
#include <cstddef>

#define NN   50000
#define EE   400000
#define DDIM 512
#define DOUT 128
#define SCAN_B 512

// ---------------------------------------------------------------------------
// Scratch (device globals: allocation-free rule)
// Activations: single fp16 plane
__device__ __half g_x  [(size_t)NN * DDIM];
__device__ __half g_a  [(size_t)NN * DDIM];
__device__ __half g_h1 [(size_t)NN * DDIM];
__device__ __half g_h2 [(size_t)NN * DDIM];
// Transposed weights [N][K] fp16 hi/lo
__device__ __half g_w1lhi[512*512], g_w1llo[512*512];
__device__ __half g_w1rhi[512*512], g_w1rlo[512*512];
__device__ __half g_w2lhi[512*512], g_w2llo[512*512];
__device__ __half g_w2rhi[512*512], g_w2rlo[512*512];
__device__ __half g_w3lhi[128*512], g_w3llo[128*512];
__device__ __half g_w3rhi[128*512], g_w3rlo[128*512];
// CSR
__device__ int g_deg[NN];
__device__ int g_rowptr[NN + 1];
__device__ int g_cursor[NN];
__device__ int g_csr[EE];
__device__ int g_bsums[(NN + SCAN_B - 1) / SCAN_B + 1];

// ---------------------------------------------------------------------------
// PTX helpers (base-arch only: ldmatrix / mma.sync / cp.async)
// ---------------------------------------------------------------------------
__device__ __forceinline__ uint32_t smem_to_u32(const void* p) {
    uint32_t a;
    asm("{ .reg .u64 t; cvta.to.shared.u64 t, %1; cvt.u32.u64 %0, t; }"
        : "=r"(a) : "l"(p));
    return a;
}

#define LDSM_X4(r0, r1, r2, r3, addr) \
    asm volatile("ldmatrix.sync.aligned.m8n8.x4.shared.b16 {%0,%1,%2,%3}, [%4];" \
        : "=r"(r0), "=r"(r1), "=r"(r2), "=r"(r3) : "r"(addr))

#define MMA_FP16(c, a, bv0, bv1) \
    asm volatile("mma.sync.aligned.m16n8k16.row.col.f32.f16.f16.f32 " \
        "{%0,%1,%2,%3}, {%4,%5,%6,%7}, {%8,%9}, {%0,%1,%2,%3};" \
        : "+f"((c)[0]), "+f"((c)[1]), "+f"((c)[2]), "+f"((c)[3]) \
        : "r"((a)[0]), "r"((a)[1]), "r"((a)[2]), "r"((a)[3]), "r"(bv0), "r"(bv1))

#define CP_ASYNC16(smem, gmem, sz) \
    asm volatile("cp.async.cg.shared.global [%0], [%1], 16, %2;" \
        :: "r"(smem), "l"(gmem), "r"(sz) : "memory")
#define CP_COMMIT() asm volatile("cp.async.commit_group;" ::: "memory")
#define CP_WAIT(n)  asm volatile("cp.async.wait_group %0;" :: "n"(n) : "memory")

// ---------------------------------------------------------------------------
// fp16 helpers
// ---------------------------------------------------------------------------
__device__ __forceinline__ void splith(float v, __half& hi, __half& lo) {
    __half h = __float2half_rn(v);
    hi = h;
    lo = __float2half_rn(v - __half2float(h));
}
__device__ __forceinline__ uint32_t pack_h2(float a, float b) {
    __half2 t = __floats2half2_rn(a, b);
    return *reinterpret_cast<uint32_t*>(&t);
}
__device__ __forceinline__ float2 unpack_h2(uint32_t u) {
    __half2 t = *reinterpret_cast<__half2*>(&u);
    return __half22float2(t);
}

// ---------------------------------------------------------------------------
// CSR construction
// ---------------------------------------------------------------------------
__global__ void zero_int_kernel(int* p, int n) {
    int i = blockIdx.x * blockDim.x + threadIdx.x;
    if (i < n) p[i] = 0;
}
__global__ void deg_kernel(const int* __restrict__ dst, int* __restrict__ deg, int E) {
    int e = blockIdx.x * blockDim.x + threadIdx.x;
    if (e < E) atomicAdd(&deg[dst[e]], 1);
}
__global__ void scan1_kernel(const int* __restrict__ deg, int* __restrict__ rowptr,
                             int* __restrict__ bsums, int M) {
    __shared__ int sh[SCAN_B];
    int tid = threadIdx.x;
    int i = blockIdx.x * SCAN_B + tid;
    int v = (i < M) ? deg[i] : 0;
    sh[tid] = v;
    __syncthreads();
#pragma unroll
    for (int off = 1; off < SCAN_B; off <<= 1) {
        int t = (tid >= off) ? sh[tid - off] : 0;
        __syncthreads();
        sh[tid] += t;
        __syncthreads();
    }
    if (i < M) rowptr[i] = sh[tid] - v;
    if (tid == SCAN_B - 1) bsums[blockIdx.x] = sh[tid];
}
__global__ void scan2_kernel(int* bsums, int* rowptr, int nblk, int M) {
    int run = 0;
    for (int b = 0; b < nblk; b++) { int t = bsums[b]; bsums[b] = run; run += t; }
    rowptr[M] = run;
}
__global__ void scan3_kernel(int* rowptr, const int* __restrict__ bsums, int M) {
    int i = blockIdx.x * blockDim.x + threadIdx.x;
    if (i < M) rowptr[i] += bsums[i / SCAN_B];
}
__global__ void csr_fill_kernel(const int* __restrict__ src, const int* __restrict__ dst,
                                const int* __restrict__ rowptr, int* __restrict__ cursor,
                                int* __restrict__ csr, int E) {
    int e = blockIdx.x * blockDim.x + threadIdx.x;
    if (e < E) {
        int d = dst[e];
        int pos = atomicAdd(&cursor[d], 1);
        csr[rowptr[d] + pos] = src[e];
    }
}

// ---------------------------------------------------------------------------
// Conversions
// ---------------------------------------------------------------------------
// fp32 x -> single fp16 plane
__global__ void convx_kernel(const float4* __restrict__ x,
                             uint2* __restrict__ xh, int n4) {
    int i = blockIdx.x * blockDim.x + threadIdx.x;
    int stride = gridDim.x * blockDim.x;
    for (; i < n4; i += stride) {
        float4 v = x[i];
        uint2 u;
        u.x = pack_h2(v.x, v.y);
        u.y = pack_h2(v.z, v.w);
        xh[i] = u;
    }
}

// Transpose + split weights: W fp32 [K][N] -> Whi/Wlo fp16 [N][K]
__global__ void wconv_kernel(const float* __restrict__ W,
                             __half* __restrict__ Whi,
                             __half* __restrict__ Wlo, int K, int N) {
    __shared__ float t[32][33];
    int nb = blockIdx.x * 32, kb = blockIdx.y * 32;
    for (int i = threadIdx.y; i < 32; i += 8)
        t[i][threadIdx.x] = W[(size_t)(kb + i) * N + nb + threadIdx.x];
    __syncthreads();
    for (int i = threadIdx.y; i < 32; i += 8) {
        float v = t[threadIdx.x][i];
        __half h, l; splith(v, h, l);
        size_t o = (size_t)(nb + i) * K + kb + threadIdx.x;
        Whi[o] = h;
        Wlo[o] = l;
    }
}

// ---------------------------------------------------------------------------
// Gather-mean on fp16: 4 nodes per block, 64 threads per node,
// one uint4 (8 halves) per thread = full 512-dim row.
// ---------------------------------------------------------------------------
__global__ void gather_mean_kernel(const __half* __restrict__ xh,
                                   const int* __restrict__ rowptr,
                                   const int* __restrict__ csr,
                                   __half* __restrict__ ah, int M) {
    int node = blockIdx.x * 4 + (threadIdx.x >> 6);
    int t    = threadIdx.x & 63;
    if (node >= M) return;
    int beg = rowptr[node], end = rowptr[node + 1];
    const uint4* XH = (const uint4*)xh;
    float a[8];
#pragma unroll
    for (int j = 0; j < 8; j++) a[j] = 0.f;

    auto accum = [&](uint4 u) {
        float2 p;
        p = unpack_h2(u.x); a[0] += p.x; a[1] += p.y;
        p = unpack_h2(u.y); a[2] += p.x; a[3] += p.y;
        p = unpack_h2(u.z); a[4] += p.x; a[5] += p.y;
        p = unpack_h2(u.w); a[6] += p.x; a[7] += p.y;
    };

    int i = beg;
    for (; i + 3 < end; i += 4) {
        int s0 = csr[i], s1 = csr[i+1], s2 = csr[i+2], s3 = csr[i+3];
        uint4 v0 = XH[(size_t)s0 * 64 + t];
        uint4 v1 = XH[(size_t)s1 * 64 + t];
        uint4 v2 = XH[(size_t)s2 * 64 + t];
        uint4 v3 = XH[(size_t)s3 * 64 + t];
        accum(v0); accum(v1); accum(v2); accum(v3);
    }
    for (; i < end; i++) {
        accum(XH[(size_t)csr[i] * 64 + t]);
    }

    float inv = 1.0f / (float)max(end - beg, 1);
    uint4 u;
    uint32_t* pu = (uint32_t*)&u;
#pragma unroll
    for (int j = 0; j < 4; j++)
        pu[j] = pack_h2(a[j*2+0] * inv, a[j*2+1] * inv);
    ((uint4*)ah)[(size_t)node * 64 + t] = u;
}

// ---------------------------------------------------------------------------
// mma.sync fp16 GEMM with exact-ish weights:
// C[M, Ntot] = A0 @ (B0hi+B0lo)^T + A1 @ (B1hi+B1lo)^T + bias (each K half 512)
// A is single fp16 plane (input quantization ~2^-12); B split hi/lo fp16.
// 2 MMA products per tile. fp32 register accumulators.
// CTA tile 128x128, 8 warps (4m x 2n), warp tile 32x64.
// K-chunk 64 halves, 2-stage cp.async pipeline, one __syncthreads per chunk.
// SMEM row stride 144B; 3 planes per stage (A, Bhi, Blo) = 55296B/stage.
// ---------------------------------------------------------------------------
template <bool FP16_RELU>
__global__ __launch_bounds__(256, 2)
void gemm_mma(const __half* __restrict__ A0, const __half* __restrict__ A1,
              const __half* __restrict__ B0hi, const __half* __restrict__ B0lo,
              const __half* __restrict__ B1hi, const __half* __restrict__ B1lo,
              const float* __restrict__ bias,
              float* __restrict__ Cf, __half* __restrict__ Ch,
              int M, int Ntot) {
    extern __shared__ char dsm[];
    constexpr int SROW  = 144;         // 64 halves = 128B data + 16B pad
    constexpr int PLANE = 128 * SROW;  // 18432 B
    constexpr int STAGE = 3 * PLANE;   // 55296 B: A, Bhi, Blo
    constexpr int OFF_A = 0, OFF_BHI = PLANE, OFF_BLO = 2*PLANE;

    const int tid  = threadIdx.x;
    const int wid  = tid >> 5;
    const int lane = tid & 31;
    const int wm = wid >> 1;
    const int wn = wid & 1;
    const int mBase = blockIdx.y * 128;
    const int nBase = blockIdx.x * 128;
    const uint32_t smem = smem_to_u32(dsm);

    // ---- async loader for one K-chunk (64 halves = 128B/row) into stage s ----
    auto issue_chunk = [&](int ch, int s) {
        const bool half = (ch >= 8);
        const char* Ap = (const char*)(half ? A1 : A0);
        const char* Bh = (const char*)(half ? B1hi : B0hi);
        const char* Bl = (const char*)(half ? B1lo : B0lo);
        const int k0b = (ch & 7) * 128;          // byte offset within 1024B row
        const uint32_t sb = smem + s * STAGE;
#pragma unroll
        for (int it = 0; it < 4; it++) {
            int c = tid + it * 256;              // 0..1023
            int row = c >> 3, q = c & 7;
            uint32_t soff = row * SROW + q * 16;
            int am = mBase + row;
            int asz = (am < M) ? 16 : 0;
            size_t ga = (size_t)(am < M ? am : 0) * 1024 + k0b + q * 16;
            CP_ASYNC16(sb + OFF_A + soff, Ap + ga, asz);
            size_t gb = (size_t)(nBase + row) * 1024 + k0b + q * 16;
            CP_ASYNC16(sb + OFF_BHI + soff, Bh + gb, 16);
            CP_ASYNC16(sb + OFF_BLO + soff, Bl + gb, 16);
        }
        CP_COMMIT();
    };

    float acc[2][8][4];
#pragma unroll
    for (int i = 0; i < 2; i++)
#pragma unroll
        for (int j = 0; j < 8; j++)
#pragma unroll
            for (int k = 0; k < 4; k++) acc[i][j][k] = 0.f;

    const int g = lane >> 3, r = lane & 7;

    issue_chunk(0, 0);
    for (int ch = 0; ch < 16; ch++) {
        const int s = ch & 1;
        CP_WAIT(0);
        __syncthreads();                 // stage s visible; stage s^1 free
        if (ch + 1 < 16) issue_chunk(ch + 1, s ^ 1);

        const uint32_t sA   = smem + s * STAGE + OFF_A;
        const uint32_t sBhi = smem + s * STAGE + OFF_BHI;
        const uint32_t sBlo = smem + s * STAGE + OFF_BLO;

#pragma unroll
        for (int ks = 0; ks < 4; ks++) {
            uint32_t ah[2][4];
#pragma unroll
            for (int mi = 0; mi < 2; mi++) {
                uint32_t arow = wm * 32 + mi * 16 + ((g & 1) << 3) + r;
                uint32_t aoff = arow * SROW + ks * 32 + (g >> 1) * 16;
                LDSM_X4(ah[mi][0], ah[mi][1], ah[mi][2], ah[mi][3], sA + aoff);
            }
#pragma unroll
            for (int j = 0; j < 4; j++) {
                uint32_t brow = wn * 64 + j * 16 + ((g >> 1) << 3) + r;
                uint32_t boff = brow * SROW + ks * 32 + (g & 1) * 16;
                uint32_t bh0, bh1, bh2, bh3, bl0, bl1, bl2, bl3;
                LDSM_X4(bh0, bh1, bh2, bh3, sBhi + boff);
                LDSM_X4(bl0, bl1, bl2, bl3, sBlo + boff);
                // acc touched every 4th MMA -> latency hidden
                MMA_FP16(acc[0][j*2+0], ah[0], bh0, bh1);
                MMA_FP16(acc[0][j*2+1], ah[0], bh2, bh3);
                MMA_FP16(acc[1][j*2+0], ah[1], bh0, bh1);
                MMA_FP16(acc[1][j*2+1], ah[1], bh2, bh3);

                MMA_FP16(acc[0][j*2+0], ah[0], bl0, bl1);
                MMA_FP16(acc[0][j*2+1], ah[0], bl2, bl3);
                MMA_FP16(acc[1][j*2+0], ah[1], bl0, bl1);
                MMA_FP16(acc[1][j*2+1], ah[1], bl2, bl3);
            }
        }
    }

    // ---- Epilogue ----
    const int qrow = lane >> 2, qcol = lane & 3;
#pragma unroll
    for (int mi = 0; mi < 2; mi++) {
#pragma unroll
        for (int ni = 0; ni < 8; ni++) {
            int row0 = mBase + wm * 32 + mi * 16 + qrow;
            int col  = nBase + wn * 64 + ni * 8 + qcol * 2;
            float2 bb = *(const float2*)(bias + col);
#pragma unroll
            for (int h = 0; h < 2; h++) {
                int row = row0 + h * 8;
                if (row >= M) continue;
                float v0 = acc[mi][ni][h*2+0] + bb.x;
                float v1 = acc[mi][ni][h*2+1] + bb.y;
                if (FP16_RELU) {
                    v0 = fmaxf(v0, 0.f); v1 = fmaxf(v1, 0.f);
                    *(uint32_t*)(Ch + (size_t)row * Ntot + col) = pack_h2(v0, v1);
                } else {
                    float2 o; o.x = v0; o.y = v1;
                    *(float2*)(Cf + (size_t)row * Ntot + col) = o;
                }
            }
        }
    }
}

// ---------------------------------------------------------------------------
// In-place log_softmax over rows of 128, one warp per row.
// ---------------------------------------------------------------------------
__global__ void log_softmax128_kernel(float* __restrict__ out, int M) {
    int row  = blockIdx.x * (blockDim.x >> 5) + (threadIdx.x >> 5);
    int lane = threadIdx.x & 31;
    if (row >= M) return;
    float4* p = (float4*)(out + (size_t)row * DOUT);
    float4 v = p[lane];
    float mx = fmaxf(fmaxf(v.x, v.y), fmaxf(v.z, v.w));
#pragma unroll
    for (int o = 16; o; o >>= 1) mx = fmaxf(mx, __shfl_xor_sync(0xffffffffu, mx, o));
    float s = expf(v.x - mx) + expf(v.y - mx) + expf(v.z - mx) + expf(v.w - mx);
#pragma unroll
    for (int o = 16; o; o >>= 1) s += __shfl_xor_sync(0xffffffffu, s, o);
    float l = mx + logf(s);
    v.x -= l; v.y -= l; v.z -= l; v.w -= l;
    p[lane] = v;
}

// ---------------------------------------------------------------------------
extern "C" void kernel_launch(void* const* d_in, const int* in_sizes, int n_in,
                              void* d_out, int out_size) {
    const float* x   = (const float*)d_in[0];
    const int*   ei  = (const int*)  d_in[1];
    const float* W1l = (const float*)d_in[2];
    const float* b1  = (const float*)d_in[3];
    const float* W1r = (const float*)d_in[4];
    const float* W2l = (const float*)d_in[5];
    const float* b2  = (const float*)d_in[6];
    const float* W2r = (const float*)d_in[7];
    const float* W3l = (const float*)d_in[8];
    const float* b3  = (const float*)d_in[9];
    const float* W3r = (const float*)d_in[10];
    float* out = (float*)d_out;

    const int E = in_sizes[1] / 2;
    const int M = in_sizes[0] / DDIM;
    const int* src = ei;
    const int* dst = ei + E;

    __half *xh,*ah,*h1,*h2;
    __half *w1lhi,*w1llo,*w1rhi,*w1rlo,*w2lhi,*w2llo,*w2rhi,*w2rlo;
    __half *w3lhi,*w3llo,*w3rhi,*w3rlo;
    int *deg,*rowptr,*cursor,*csr,*bsums;
    cudaGetSymbolAddress((void**)&xh, g_x);
    cudaGetSymbolAddress((void**)&ah, g_a);
    cudaGetSymbolAddress((void**)&h1, g_h1);
    cudaGetSymbolAddress((void**)&h2, g_h2);
    cudaGetSymbolAddress((void**)&w1lhi, g_w1lhi); cudaGetSymbolAddress((void**)&w1llo, g_w1llo);
    cudaGetSymbolAddress((void**)&w1rhi, g_w1rhi); cudaGetSymbolAddress((void**)&w1rlo, g_w1rlo);
    cudaGetSymbolAddress((void**)&w2lhi, g_w2lhi); cudaGetSymbolAddress((void**)&w2llo, g_w2llo);
    cudaGetSymbolAddress((void**)&w2rhi, g_w2rhi); cudaGetSymbolAddress((void**)&w2rlo, g_w2rlo);
    cudaGetSymbolAddress((void**)&w3lhi, g_w3lhi); cudaGetSymbolAddress((void**)&w3llo, g_w3llo);
    cudaGetSymbolAddress((void**)&w3rhi, g_w3rhi); cudaGetSymbolAddress((void**)&w3rlo, g_w3rlo);
    cudaGetSymbolAddress((void**)&deg,    g_deg);
    cudaGetSymbolAddress((void**)&rowptr, g_rowptr);
    cudaGetSymbolAddress((void**)&cursor, g_cursor);
    cudaGetSymbolAddress((void**)&csr,    g_csr);
    cudaGetSymbolAddress((void**)&bsums,  g_bsums);

    const int nblk = (M + SCAN_B - 1) / SCAN_B;

    const int SMEM_GEMM = 2 * 3 * 128 * 144;  // 110592 B -> 2 CTAs/SM
    cudaFuncSetAttribute(gemm_mma<true>,  cudaFuncAttributeMaxDynamicSharedMemorySize, SMEM_GEMM);
    cudaFuncSetAttribute(gemm_mma<false>, cudaFuncAttributeMaxDynamicSharedMemorySize, SMEM_GEMM);

    // ---- CSR build ----
    zero_int_kernel<<<(M + 255) / 256, 256>>>(deg, M);
    zero_int_kernel<<<(M + 255) / 256, 256>>>(cursor, M);
    deg_kernel<<<(E + 255) / 256, 256>>>(dst, deg, E);
    scan1_kernel<<<nblk, SCAN_B>>>(deg, rowptr, bsums, M);
    scan2_kernel<<<1, 1>>>(bsums, rowptr, nblk, M);
    scan3_kernel<<<(M + 255) / 256, 256>>>(rowptr, bsums, M);
    csr_fill_kernel<<<(E + 255) / 256, 256>>>(src, dst, rowptr, cursor, csr, E);

    // ---- Conversions ----
    convx_kernel<<<2048, 256>>>((const float4*)x, (uint2*)xh, M * DDIM / 4);
    wconv_kernel<<<dim3(512/32, 512/32), dim3(32, 8)>>>(W1l, w1lhi, w1llo, 512, 512);
    wconv_kernel<<<dim3(512/32, 512/32), dim3(32, 8)>>>(W1r, w1rhi, w1rlo, 512, 512);
    wconv_kernel<<<dim3(512/32, 512/32), dim3(32, 8)>>>(W2l, w2lhi, w2llo, 512, 512);
    wconv_kernel<<<dim3(512/32, 512/32), dim3(32, 8)>>>(W2r, w2rhi, w2rlo, 512, 512);
    wconv_kernel<<<dim3(128/32, 512/32), dim3(32, 8)>>>(W3l, w3lhi, w3llo, 512, 128);
    wconv_kernel<<<dim3(128/32, 512/32), dim3(32, 8)>>>(W3r, w3rhi, w3rlo, 512, 128);

    const int mTiles = (M + 127) / 128;
    const int gBlocks = (M + 3) / 4;

    // ---- Layer 1 ----
    gather_mean_kernel<<<gBlocks, 256>>>(xh, rowptr, csr, ah, M);
    gemm_mma<true><<<dim3(4, mTiles), 256, SMEM_GEMM>>>(
        ah, xh, w1lhi, w1llo, w1rhi, w1rlo, b1, nullptr, h1, M, DDIM);

    // ---- Layer 2 ----
    gather_mean_kernel<<<gBlocks, 256>>>(h1, rowptr, csr, ah, M);
    gemm_mma<true><<<dim3(4, mTiles), 256, SMEM_GEMM>>>(
        ah, h1, w2lhi, w2llo, w2rhi, w2rlo, b2, nullptr, h2, M, DDIM);

    // ---- Layer 3 ----
    gather_mean_kernel<<<gBlocks, 256>>>(h2, rowptr, csr, ah, M);
    gemm_mma<false><<<dim3(1, mTiles), 256, SMEM_GEMM>>>(
        ah, h2, w3lhi, w3llo, w3rhi, w3rlo, b3, out, nullptr, M, DOUT);

    // log_softmax in place on d_out
    log_softmax128_kernel<<<(M + 7) / 8, 256>>>(out, M);
    (void)n_in; (void)out_size;
}

// round 9
// speedup vs baseline: 8.5790x; 2.0574x over previous
#include <cuda_runtime.h>
#include <cuda_fp16.h>
#include <cstdint>
#include <cstddef>

#define NN   50000
#define EE   400000
#define DDIM 512
#define DOUT 128
#define SCAN_B 512

// ---------------------------------------------------------------------------
// Scratch (device globals: allocation-free rule)
// Activations: single fp16 plane
__device__ __half g_x  [(size_t)NN * DDIM];
__device__ __half g_a  [(size_t)NN * DDIM];
__device__ __half g_h1 [(size_t)NN * DDIM];
__device__ __half g_h2 [(size_t)NN * DDIM];
// Transposed weights [N][K] fp16 (layers 1/2: hi only; layer 3: hi+lo)
__device__ __half g_w1l[512*512];
__device__ __half g_w1r[512*512];
__device__ __half g_w2l[512*512];
__device__ __half g_w2r[512*512];
__device__ __half g_w3lhi[128*512], g_w3llo[128*512];
__device__ __half g_w3rhi[128*512], g_w3rlo[128*512];
// CSR
__device__ int g_deg[NN];
__device__ int g_rowptr[NN + 1];
__device__ int g_cursor[NN];
__device__ int g_csr[EE];
__device__ int g_bsums[(NN + SCAN_B - 1) / SCAN_B + 1];

// ---------------------------------------------------------------------------
// PTX helpers (base-arch only: ldmatrix / mma.sync / cp.async)
// ---------------------------------------------------------------------------
__device__ __forceinline__ uint32_t smem_to_u32(const void* p) {
    uint32_t a;
    asm("{ .reg .u64 t; cvta.to.shared.u64 t, %1; cvt.u32.u64 %0, t; }"
        : "=r"(a) : "l"(p));
    return a;
}

#define LDSM_X4(r0, r1, r2, r3, addr) \
    asm volatile("ldmatrix.sync.aligned.m8n8.x4.shared.b16 {%0,%1,%2,%3}, [%4];" \
        : "=r"(r0), "=r"(r1), "=r"(r2), "=r"(r3) : "r"(addr))

#define MMA_FP16(c, a, bv0, bv1) \
    asm volatile("mma.sync.aligned.m16n8k16.row.col.f32.f16.f16.f32 " \
        "{%0,%1,%2,%3}, {%4,%5,%6,%7}, {%8,%9}, {%0,%1,%2,%3};" \
        : "+f"((c)[0]), "+f"((c)[1]), "+f"((c)[2]), "+f"((c)[3]) \
        : "r"((a)[0]), "r"((a)[1]), "r"((a)[2]), "r"((a)[3]), "r"(bv0), "r"(bv1))

#define CP_ASYNC16(smem, gmem, sz) \
    asm volatile("cp.async.cg.shared.global [%0], [%1], 16, %2;" \
        :: "r"(smem), "l"(gmem), "r"(sz) : "memory")
#define CP_COMMIT() asm volatile("cp.async.commit_group;" ::: "memory")
#define CP_WAIT(n)  asm volatile("cp.async.wait_group %0;" :: "n"(n) : "memory")

// ---------------------------------------------------------------------------
// fp16 helpers
// ---------------------------------------------------------------------------
__device__ __forceinline__ void splith(float v, __half& hi, __half& lo) {
    __half h = __float2half_rn(v);
    hi = h;
    lo = __float2half_rn(v - __half2float(h));
}
__device__ __forceinline__ uint32_t pack_h2(float a, float b) {
    __half2 t = __floats2half2_rn(a, b);
    return *reinterpret_cast<uint32_t*>(&t);
}
__device__ __forceinline__ float2 unpack_h2(uint32_t u) {
    __half2 t = *reinterpret_cast<__half2*>(&u);
    return __half22float2(t);
}

// ---------------------------------------------------------------------------
// CSR construction
// ---------------------------------------------------------------------------
__global__ void zero_int_kernel(int* p, int n) {
    int i = blockIdx.x * blockDim.x + threadIdx.x;
    if (i < n) p[i] = 0;
}
__global__ void deg_kernel(const int* __restrict__ dst, int* __restrict__ deg, int E) {
    int e = blockIdx.x * blockDim.x + threadIdx.x;
    if (e < E) atomicAdd(&deg[dst[e]], 1);
}
__global__ void scan1_kernel(const int* __restrict__ deg, int* __restrict__ rowptr,
                             int* __restrict__ bsums, int M) {
    __shared__ int sh[SCAN_B];
    int tid = threadIdx.x;
    int i = blockIdx.x * SCAN_B + tid;
    int v = (i < M) ? deg[i] : 0;
    sh[tid] = v;
    __syncthreads();
#pragma unroll
    for (int off = 1; off < SCAN_B; off <<= 1) {
        int t = (tid >= off) ? sh[tid - off] : 0;
        __syncthreads();
        sh[tid] += t;
        __syncthreads();
    }
    if (i < M) rowptr[i] = sh[tid] - v;
    if (tid == SCAN_B - 1) bsums[blockIdx.x] = sh[tid];
}
__global__ void scan2_kernel(int* bsums, int* rowptr, int nblk, int M) {
    int run = 0;
    for (int b = 0; b < nblk; b++) { int t = bsums[b]; bsums[b] = run; run += t; }
    rowptr[M] = run;
}
__global__ void scan3_kernel(int* rowptr, const int* __restrict__ bsums, int M) {
    int i = blockIdx.x * blockDim.x + threadIdx.x;
    if (i < M) rowptr[i] += bsums[i / SCAN_B];
}
__global__ void csr_fill_kernel(const int* __restrict__ src, const int* __restrict__ dst,
                                const int* __restrict__ rowptr, int* __restrict__ cursor,
                                int* __restrict__ csr, int E) {
    int e = blockIdx.x * blockDim.x + threadIdx.x;
    if (e < E) {
        int d = dst[e];
        int pos = atomicAdd(&cursor[d], 1);
        csr[rowptr[d] + pos] = src[e];
    }
}

// ---------------------------------------------------------------------------
// Conversions
// ---------------------------------------------------------------------------
// fp32 x -> single fp16 plane
__global__ void convx_kernel(const float4* __restrict__ x,
                             uint2* __restrict__ xh, int n4) {
    int i = blockIdx.x * blockDim.x + threadIdx.x;
    int stride = gridDim.x * blockDim.x;
    for (; i < n4; i += stride) {
        float4 v = x[i];
        uint2 u;
        u.x = pack_h2(v.x, v.y);
        u.y = pack_h2(v.z, v.w);
        xh[i] = u;
    }
}

// Transpose weights: W fp32 [K][N] -> W fp16 [N][K] (single plane)
__global__ void wconv1_kernel(const float* __restrict__ W,
                              __half* __restrict__ Wh, int K, int N) {
    __shared__ float t[32][33];
    int nb = blockIdx.x * 32, kb = blockIdx.y * 32;
    for (int i = threadIdx.y; i < 32; i += 8)
        t[i][threadIdx.x] = W[(size_t)(kb + i) * N + nb + threadIdx.x];
    __syncthreads();
    for (int i = threadIdx.y; i < 32; i += 8) {
        float v = t[threadIdx.x][i];
        size_t o = (size_t)(nb + i) * K + kb + threadIdx.x;
        Wh[o] = __float2half_rn(v);
    }
}

// Transpose + split weights: W fp32 [K][N] -> Whi/Wlo fp16 [N][K]
__global__ void wconv2_kernel(const float* __restrict__ W,
                              __half* __restrict__ Whi,
                              __half* __restrict__ Wlo, int K, int N) {
    __shared__ float t[32][33];
    int nb = blockIdx.x * 32, kb = blockIdx.y * 32;
    for (int i = threadIdx.y; i < 32; i += 8)
        t[i][threadIdx.x] = W[(size_t)(kb + i) * N + nb + threadIdx.x];
    __syncthreads();
    for (int i = threadIdx.y; i < 32; i += 8) {
        float v = t[threadIdx.x][i];
        __half h, l; splith(v, h, l);
        size_t o = (size_t)(nb + i) * K + kb + threadIdx.x;
        Whi[o] = h;
        Wlo[o] = l;
    }
}

// ---------------------------------------------------------------------------
// Gather-mean on fp16: 4 nodes per block, 64 threads per node,
// one uint4 (8 halves) per thread = full 512-dim row.
// ---------------------------------------------------------------------------
__global__ void gather_mean_kernel(const __half* __restrict__ xh,
                                   const int* __restrict__ rowptr,
                                   const int* __restrict__ csr,
                                   __half* __restrict__ ah, int M) {
    int node = blockIdx.x * 4 + (threadIdx.x >> 6);
    int t    = threadIdx.x & 63;
    if (node >= M) return;
    int beg = rowptr[node], end = rowptr[node + 1];
    const uint4* XH = (const uint4*)xh;
    float a[8];
#pragma unroll
    for (int j = 0; j < 8; j++) a[j] = 0.f;

    auto accum = [&](uint4 u) {
        float2 p;
        p = unpack_h2(u.x); a[0] += p.x; a[1] += p.y;
        p = unpack_h2(u.y); a[2] += p.x; a[3] += p.y;
        p = unpack_h2(u.z); a[4] += p.x; a[5] += p.y;
        p = unpack_h2(u.w); a[6] += p.x; a[7] += p.y;
    };

    int i = beg;
    for (; i + 3 < end; i += 4) {
        int s0 = csr[i], s1 = csr[i+1], s2 = csr[i+2], s3 = csr[i+3];
        uint4 v0 = XH[(size_t)s0 * 64 + t];
        uint4 v1 = XH[(size_t)s1 * 64 + t];
        uint4 v2 = XH[(size_t)s2 * 64 + t];
        uint4 v3 = XH[(size_t)s3 * 64 + t];
        accum(v0); accum(v1); accum(v2); accum(v3);
    }
    for (; i < end; i++) {
        accum(XH[(size_t)csr[i] * 64 + t]);
    }

    float inv = 1.0f / (float)max(end - beg, 1);
    uint4 u;
    uint32_t* pu = (uint32_t*)&u;
#pragma unroll
    for (int j = 0; j < 4; j++)
        pu[j] = pack_h2(a[j*2+0] * inv, a[j*2+1] * inv);
    ((uint4*)ah)[(size_t)node * 64 + t] = u;
}

// ---------------------------------------------------------------------------
// mma.sync fp16 GEMM:
// C[M, Ntot] = A0 @ B0^T + A1 @ B1^T + bias   (each K half 512)
// USE_LO=false: B plain fp16, 1 MMA product (layers 1/2).
// USE_LO=true:  B split hi/lo, 2 MMA products (layer 3, exact-ish weights).
// CTA tile 128x128, 8 warps (4m x 2n), warp tile 32x64, fp32 accumulators.
// K-chunk 64 halves, 2-stage cp.async pipeline, one __syncthreads per chunk.
// SMEM row stride 144B (128B data + 16B pad): ldmatrix conflict-free.
// ---------------------------------------------------------------------------
template <bool FP16_RELU, bool USE_LO>
__global__ __launch_bounds__(256, 2)
void gemm_mma(const __half* __restrict__ A0, const __half* __restrict__ A1,
              const __half* __restrict__ B0hi, const __half* __restrict__ B0lo,
              const __half* __restrict__ B1hi, const __half* __restrict__ B1lo,
              const float* __restrict__ bias,
              float* __restrict__ Cf, __half* __restrict__ Ch,
              int M, int Ntot) {
    extern __shared__ char dsm[];
    constexpr int SROW   = 144;         // 64 halves = 128B data + 16B pad
    constexpr int PLANE  = 128 * SROW;  // 18432 B
    constexpr int NPLANE = USE_LO ? 3 : 2;
    constexpr int STAGE  = NPLANE * PLANE;
    constexpr int OFF_A = 0, OFF_BHI = PLANE, OFF_BLO = 2*PLANE;

    const int tid  = threadIdx.x;
    const int wid  = tid >> 5;
    const int lane = tid & 31;
    const int wm = wid >> 1;
    const int wn = wid & 1;
    const int mBase = blockIdx.y * 128;
    const int nBase = blockIdx.x * 128;
    const uint32_t smem = smem_to_u32(dsm);

    // ---- async loader for one K-chunk (64 halves = 128B/row) into stage s ----
    auto issue_chunk = [&](int ch, int s) {
        const bool half = (ch >= 8);
        const char* Ap = (const char*)(half ? A1 : A0);
        const char* Bh = (const char*)(half ? B1hi : B0hi);
        const char* Bl = (const char*)(half ? B1lo : B0lo);
        const int k0b = (ch & 7) * 128;          // byte offset within 1024B row
        const uint32_t sb = smem + s * STAGE;
#pragma unroll
        for (int it = 0; it < 4; it++) {
            int c = tid + it * 256;              // 0..1023
            int row = c >> 3, q = c & 7;
            uint32_t soff = row * SROW + q * 16;
            int am = mBase + row;
            int asz = (am < M) ? 16 : 0;
            size_t ga = (size_t)(am < M ? am : 0) * 1024 + k0b + q * 16;
            CP_ASYNC16(sb + OFF_A + soff, Ap + ga, asz);
            size_t gb = (size_t)(nBase + row) * 1024 + k0b + q * 16;
            CP_ASYNC16(sb + OFF_BHI + soff, Bh + gb, 16);
            if (USE_LO) CP_ASYNC16(sb + OFF_BLO + soff, Bl + gb, 16);
        }
        CP_COMMIT();
    };

    float acc[2][8][4];
#pragma unroll
    for (int i = 0; i < 2; i++)
#pragma unroll
        for (int j = 0; j < 8; j++)
#pragma unroll
            for (int k = 0; k < 4; k++) acc[i][j][k] = 0.f;

    const int g = lane >> 3, r = lane & 7;

    issue_chunk(0, 0);
    for (int ch = 0; ch < 16; ch++) {
        const int s = ch & 1;
        CP_WAIT(0);
        __syncthreads();                 // stage s visible; stage s^1 free
        if (ch + 1 < 16) issue_chunk(ch + 1, s ^ 1);

        const uint32_t sA   = smem + s * STAGE + OFF_A;
        const uint32_t sBhi = smem + s * STAGE + OFF_BHI;
        const uint32_t sBlo = smem + s * STAGE + OFF_BLO;

#pragma unroll
        for (int ks = 0; ks < 4; ks++) {
            uint32_t ah[2][4];
#pragma unroll
            for (int mi = 0; mi < 2; mi++) {
                uint32_t arow = wm * 32 + mi * 16 + ((g & 1) << 3) + r;
                uint32_t aoff = arow * SROW + ks * 32 + (g >> 1) * 16;
                LDSM_X4(ah[mi][0], ah[mi][1], ah[mi][2], ah[mi][3], sA + aoff);
            }
#pragma unroll
            for (int j = 0; j < 4; j++) {
                uint32_t brow = wn * 64 + j * 16 + ((g >> 1) << 3) + r;
                uint32_t boff = brow * SROW + ks * 32 + (g & 1) * 16;
                uint32_t bh0, bh1, bh2, bh3;
                LDSM_X4(bh0, bh1, bh2, bh3, sBhi + boff);
                // all 4 accs distinct -> no back-to-back RAW
                MMA_FP16(acc[0][j*2+0], ah[0], bh0, bh1);
                MMA_FP16(acc[0][j*2+1], ah[0], bh2, bh3);
                MMA_FP16(acc[1][j*2+0], ah[1], bh0, bh1);
                MMA_FP16(acc[1][j*2+1], ah[1], bh2, bh3);
                if (USE_LO) {
                    uint32_t bl0, bl1, bl2, bl3;
                    LDSM_X4(bl0, bl1, bl2, bl3, sBlo + boff);
                    MMA_FP16(acc[0][j*2+0], ah[0], bl0, bl1);
                    MMA_FP16(acc[0][j*2+1], ah[0], bl2, bl3);
                    MMA_FP16(acc[1][j*2+0], ah[1], bl0, bl1);
                    MMA_FP16(acc[1][j*2+1], ah[1], bl2, bl3);
                }
            }
        }
    }

    // ---- Epilogue ----
    const int qrow = lane >> 2, qcol = lane & 3;
#pragma unroll
    for (int mi = 0; mi < 2; mi++) {
#pragma unroll
        for (int ni = 0; ni < 8; ni++) {
            int row0 = mBase + wm * 32 + mi * 16 + qrow;
            int col  = nBase + wn * 64 + ni * 8 + qcol * 2;
            float2 bb = *(const float2*)(bias + col);
#pragma unroll
            for (int h = 0; h < 2; h++) {
                int row = row0 + h * 8;
                if (row >= M) continue;
                float v0 = acc[mi][ni][h*2+0] + bb.x;
                float v1 = acc[mi][ni][h*2+1] + bb.y;
                if (FP16_RELU) {
                    v0 = fmaxf(v0, 0.f); v1 = fmaxf(v1, 0.f);
                    *(uint32_t*)(Ch + (size_t)row * Ntot + col) = pack_h2(v0, v1);
                } else {
                    float2 o; o.x = v0; o.y = v1;
                    *(float2*)(Cf + (size_t)row * Ntot + col) = o;
                }
            }
        }
    }
}

// ---------------------------------------------------------------------------
// In-place log_softmax over rows of 128, one warp per row.
// ---------------------------------------------------------------------------
__global__ void log_softmax128_kernel(float* __restrict__ out, int M) {
    int row  = blockIdx.x * (blockDim.x >> 5) + (threadIdx.x >> 5);
    int lane = threadIdx.x & 31;
    if (row >= M) return;
    float4* p = (float4*)(out + (size_t)row * DOUT);
    float4 v = p[lane];
    float mx = fmaxf(fmaxf(v.x, v.y), fmaxf(v.z, v.w));
#pragma unroll
    for (int o = 16; o; o >>= 1) mx = fmaxf(mx, __shfl_xor_sync(0xffffffffu, mx, o));
    float s = expf(v.x - mx) + expf(v.y - mx) + expf(v.z - mx) + expf(v.w - mx);
#pragma unroll
    for (int o = 16; o; o >>= 1) s += __shfl_xor_sync(0xffffffffu, s, o);
    float l = mx + logf(s);
    v.x -= l; v.y -= l; v.z -= l; v.w -= l;
    p[lane] = v;
}

// ---------------------------------------------------------------------------
extern "C" void kernel_launch(void* const* d_in, const int* in_sizes, int n_in,
                              void* d_out, int out_size) {
    const float* x   = (const float*)d_in[0];
    const int*   ei  = (const int*)  d_in[1];
    const float* W1l = (const float*)d_in[2];
    const float* b1  = (const float*)d_in[3];
    const float* W1r = (const float*)d_in[4];
    const float* W2l = (const float*)d_in[5];
    const float* b2  = (const float*)d_in[6];
    const float* W2r = (const float*)d_in[7];
    const float* W3l = (const float*)d_in[8];
    const float* b3  = (const float*)d_in[9];
    const float* W3r = (const float*)d_in[10];
    float* out = (float*)d_out;

    const int E = in_sizes[1] / 2;
    const int M = in_sizes[0] / DDIM;
    const int* src = ei;
    const int* dst = ei + E;

    __half *xh,*ah,*h1,*h2;
    __half *w1l,*w1r,*w2l,*w2r;
    __half *w3lhi,*w3llo,*w3rhi,*w3rlo;
    int *deg,*rowptr,*cursor,*csr,*bsums;
    cudaGetSymbolAddress((void**)&xh, g_x);
    cudaGetSymbolAddress((void**)&ah, g_a);
    cudaGetSymbolAddress((void**)&h1, g_h1);
    cudaGetSymbolAddress((void**)&h2, g_h2);
    cudaGetSymbolAddress((void**)&w1l, g_w1l);
    cudaGetSymbolAddress((void**)&w1r, g_w1r);
    cudaGetSymbolAddress((void**)&w2l, g_w2l);
    cudaGetSymbolAddress((void**)&w2r, g_w2r);
    cudaGetSymbolAddress((void**)&w3lhi, g_w3lhi); cudaGetSymbolAddress((void**)&w3llo, g_w3llo);
    cudaGetSymbolAddress((void**)&w3rhi, g_w3rhi); cudaGetSymbolAddress((void**)&w3rlo, g_w3rlo);
    cudaGetSymbolAddress((void**)&deg,    g_deg);
    cudaGetSymbolAddress((void**)&rowptr, g_rowptr);
    cudaGetSymbolAddress((void**)&cursor, g_cursor);
    cudaGetSymbolAddress((void**)&csr,    g_csr);
    cudaGetSymbolAddress((void**)&bsums,  g_bsums);

    const int nblk = (M + SCAN_B - 1) / SCAN_B;

    const int SMEM_1P = 2 * 2 * 128 * 144;  // 73728 B  (layers 1/2)
    const int SMEM_2P = 2 * 3 * 128 * 144;  // 110592 B (layer 3)
    cudaFuncSetAttribute(gemm_mma<true,  false>, cudaFuncAttributeMaxDynamicSharedMemorySize, SMEM_1P);
    cudaFuncSetAttribute(gemm_mma<false, true>,  cudaFuncAttributeMaxDynamicSharedMemorySize, SMEM_2P);

    // ---- CSR build ----
    zero_int_kernel<<<(M + 255) / 256, 256>>>(deg, M);
    zero_int_kernel<<<(M + 255) / 256, 256>>>(cursor, M);
    deg_kernel<<<(E + 255) / 256, 256>>>(dst, deg, E);
    scan1_kernel<<<nblk, SCAN_B>>>(deg, rowptr, bsums, M);
    scan2_kernel<<<1, 1>>>(bsums, rowptr, nblk, M);
    scan3_kernel<<<(M + 255) / 256, 256>>>(rowptr, bsums, M);
    csr_fill_kernel<<<(E + 255) / 256, 256>>>(src, dst, rowptr, cursor, csr, E);

    // ---- Conversions ----
    convx_kernel<<<2048, 256>>>((const float4*)x, (uint2*)xh, M * DDIM / 4);
    wconv1_kernel<<<dim3(512/32, 512/32), dim3(32, 8)>>>(W1l, w1l, 512, 512);
    wconv1_kernel<<<dim3(512/32, 512/32), dim3(32, 8)>>>(W1r, w1r, 512, 512);
    wconv1_kernel<<<dim3(512/32, 512/32), dim3(32, 8)>>>(W2l, w2l, 512, 512);
    wconv1_kernel<<<dim3(512/32, 512/32), dim3(32, 8)>>>(W2r, w2r, 512, 512);
    wconv2_kernel<<<dim3(128/32, 512/32), dim3(32, 8)>>>(W3l, w3lhi, w3llo, 512, 128);
    wconv2_kernel<<<dim3(128/32, 512/32), dim3(32, 8)>>>(W3r, w3rhi, w3rlo, 512, 128);

    const int mTiles = (M + 127) / 128;
    const int gBlocks = (M + 3) / 4;

    // ---- Layer 1 ----
    gather_mean_kernel<<<gBlocks, 256>>>(xh, rowptr, csr, ah, M);
    gemm_mma<true, false><<<dim3(4, mTiles), 256, SMEM_1P>>>(
        ah, xh, w1l, nullptr, w1r, nullptr, b1, nullptr, h1, M, DDIM);

    // ---- Layer 2 ----
    gather_mean_kernel<<<gBlocks, 256>>>(h1, rowptr, csr, ah, M);
    gemm_mma<true, false><<<dim3(4, mTiles), 256, SMEM_1P>>>(
        ah, h1, w2l, nullptr, w2r, nullptr, b2, nullptr, h2, M, DDIM);

    // ---- Layer 3 (keep hi+lo weights for output precision) ----
    gather_mean_kernel<<<gBlocks, 256>>>(h2, rowptr, csr, ah, M);
    gemm_mma<false, true><<<dim3(1, mTiles), 256, SMEM_2P>>>(
        ah, h2, w3lhi, w3llo, w3rhi, w3rlo, b3, out, nullptr, M, DOUT);

    // log_softmax in place on d_out
    log_softmax128_kernel<<<(M + 7) / 8, 256>>>(out, M);
    (void)n_in; (void)out_size;
}

// round 10
// speedup vs baseline: 9.2899x; 1.0829x over previous
#include <cuda_runtime.h>
#include <cuda_fp16.h>
#include <cstdint>
#include <cstddef>

#define NN   50000
#define EE   400000
#define DDIM 512
#define DOUT 128
#define SCAN_B 512

// ---------------------------------------------------------------------------
// Scratch (device globals: allocation-free rule)
// Activations: single fp16 plane
__device__ __half g_x  [(size_t)NN * DDIM];
__device__ __half g_a  [(size_t)NN * DDIM];
__device__ __half g_h1 [(size_t)NN * DDIM];
__device__ __half g_h2 [(size_t)NN * DDIM];
// Transposed weights [N][K] fp16 (all single-plane now)
__device__ __half g_w1l[512*512];
__device__ __half g_w1r[512*512];
__device__ __half g_w2l[512*512];
__device__ __half g_w2r[512*512];
__device__ __half g_w3l[128*512];
__device__ __half g_w3r[128*512];
// CSR
__device__ int g_deg[NN];
__device__ int g_rowptr[NN + 1];
__device__ int g_cursor[NN];
__device__ int g_csr[EE];
__device__ int g_bsums[(NN + SCAN_B - 1) / SCAN_B + 1];

// ---------------------------------------------------------------------------
// PTX helpers (base-arch only: ldmatrix / mma.sync / cp.async)
// ---------------------------------------------------------------------------
__device__ __forceinline__ uint32_t smem_to_u32(const void* p) {
    uint32_t a;
    asm("{ .reg .u64 t; cvta.to.shared.u64 t, %1; cvt.u32.u64 %0, t; }"
        : "=r"(a) : "l"(p));
    return a;
}

#define LDSM_X4(r0, r1, r2, r3, addr) \
    asm volatile("ldmatrix.sync.aligned.m8n8.x4.shared.b16 {%0,%1,%2,%3}, [%4];" \
        : "=r"(r0), "=r"(r1), "=r"(r2), "=r"(r3) : "r"(addr))

#define MMA_FP16(c, a, bv0, bv1) \
    asm volatile("mma.sync.aligned.m16n8k16.row.col.f32.f16.f16.f32 " \
        "{%0,%1,%2,%3}, {%4,%5,%6,%7}, {%8,%9}, {%0,%1,%2,%3};" \
        : "+f"((c)[0]), "+f"((c)[1]), "+f"((c)[2]), "+f"((c)[3]) \
        : "r"((a)[0]), "r"((a)[1]), "r"((a)[2]), "r"((a)[3]), "r"(bv0), "r"(bv1))

#define CP_ASYNC16(smem, gmem, sz) \
    asm volatile("cp.async.cg.shared.global [%0], [%1], 16, %2;" \
        :: "r"(smem), "l"(gmem), "r"(sz) : "memory")
#define CP_COMMIT() asm volatile("cp.async.commit_group;" ::: "memory")
#define CP_WAIT(n)  asm volatile("cp.async.wait_group %0;" :: "n"(n) : "memory")

// ---------------------------------------------------------------------------
// fp16 helpers
// ---------------------------------------------------------------------------
__device__ __forceinline__ uint32_t pack_h2(float a, float b) {
    __half2 t = __floats2half2_rn(a, b);
    return *reinterpret_cast<uint32_t*>(&t);
}
__device__ __forceinline__ float2 unpack_h2(uint32_t u) {
    __half2 t = *reinterpret_cast<__half2*>(&u);
    return __half22float2(t);
}

// ---------------------------------------------------------------------------
// CSR construction
// ---------------------------------------------------------------------------
__global__ void zero2_int_kernel(int* p1, int* p2, int n) {
    int i = blockIdx.x * blockDim.x + threadIdx.x;
    if (i < n) { p1[i] = 0; p2[i] = 0; }
}
__global__ void deg_kernel(const int* __restrict__ dst, int* __restrict__ deg, int E) {
    int e = blockIdx.x * blockDim.x + threadIdx.x;
    if (e < E) atomicAdd(&deg[dst[e]], 1);
}
__global__ void scan1_kernel(const int* __restrict__ deg, int* __restrict__ rowptr,
                             int* __restrict__ bsums, int M) {
    __shared__ int sh[SCAN_B];
    int tid = threadIdx.x;
    int i = blockIdx.x * SCAN_B + tid;
    int v = (i < M) ? deg[i] : 0;
    sh[tid] = v;
    __syncthreads();
#pragma unroll
    for (int off = 1; off < SCAN_B; off <<= 1) {
        int t = (tid >= off) ? sh[tid - off] : 0;
        __syncthreads();
        sh[tid] += t;
        __syncthreads();
    }
    if (i < M) rowptr[i] = sh[tid] - v;
    if (tid == SCAN_B - 1) bsums[blockIdx.x] = sh[tid];
}
__global__ void scan2_kernel(int* bsums, int* rowptr, int nblk, int M) {
    int run = 0;
    for (int b = 0; b < nblk; b++) { int t = bsums[b]; bsums[b] = run; run += t; }
    rowptr[M] = run;
}
__global__ void scan3_kernel(int* rowptr, const int* __restrict__ bsums, int M) {
    int i = blockIdx.x * blockDim.x + threadIdx.x;
    if (i < M) rowptr[i] += bsums[i / SCAN_B];
}
__global__ void csr_fill_kernel(const int* __restrict__ src, const int* __restrict__ dst,
                                const int* __restrict__ rowptr, int* __restrict__ cursor,
                                int* __restrict__ csr, int E) {
    int e = blockIdx.x * blockDim.x + threadIdx.x;
    if (e < E) {
        int d = dst[e];
        int pos = atomicAdd(&cursor[d], 1);
        csr[rowptr[d] + pos] = src[e];
    }
}

// ---------------------------------------------------------------------------
// Conversions
// ---------------------------------------------------------------------------
// fp32 x -> single fp16 plane
__global__ void convx_kernel(const float4* __restrict__ x,
                             uint2* __restrict__ xh, int n4) {
    int i = blockIdx.x * blockDim.x + threadIdx.x;
    int stride = gridDim.x * blockDim.x;
    for (; i < n4; i += stride) {
        float4 v = x[i];
        uint2 u;
        u.x = pack_h2(v.x, v.y);
        u.y = pack_h2(v.z, v.w);
        xh[i] = u;
    }
}

// Batched transpose of all 6 weights: W fp32 [K][N] -> W fp16 [N][K].
// blockIdx.z selects which matrix; z=4,5 have N=128 (extra x-blocks return).
__global__ void wconv_all_kernel(const float* __restrict__ W1l, const float* __restrict__ W1r,
                                 const float* __restrict__ W2l, const float* __restrict__ W2r,
                                 const float* __restrict__ W3l, const float* __restrict__ W3r,
                                 __half* __restrict__ o1l, __half* __restrict__ o1r,
                                 __half* __restrict__ o2l, __half* __restrict__ o2r,
                                 __half* __restrict__ o3l, __half* __restrict__ o3r) {
    const float* W; __half* O; int N;
    switch (blockIdx.z) {
        case 0: W = W1l; O = o1l; N = 512; break;
        case 1: W = W1r; O = o1r; N = 512; break;
        case 2: W = W2l; O = o2l; N = 512; break;
        case 3: W = W2r; O = o2r; N = 512; break;
        case 4: W = W3l; O = o3l; N = 128; break;
        default: W = W3r; O = o3r; N = 128; break;
    }
    const int K = 512;
    int nb = blockIdx.x * 32, kb = blockIdx.y * 32;
    if (nb >= N) return;
    __shared__ float t[32][33];
    for (int i = threadIdx.y; i < 32; i += 8)
        t[i][threadIdx.x] = W[(size_t)(kb + i) * N + nb + threadIdx.x];
    __syncthreads();
    for (int i = threadIdx.y; i < 32; i += 8) {
        float v = t[threadIdx.x][i];
        size_t o = (size_t)(nb + i) * K + kb + threadIdx.x;
        O[o] = __float2half_rn(v);
    }
}

// ---------------------------------------------------------------------------
// Gather-mean on fp16: 4 nodes per block, 64 threads per node,
// one uint4 (8 halves) per thread = full 512-dim row.
// ---------------------------------------------------------------------------
__global__ void gather_mean_kernel(const __half* __restrict__ xh,
                                   const int* __restrict__ rowptr,
                                   const int* __restrict__ csr,
                                   __half* __restrict__ ah, int M) {
    int node = blockIdx.x * 4 + (threadIdx.x >> 6);
    int t    = threadIdx.x & 63;
    if (node >= M) return;
    int beg = rowptr[node], end = rowptr[node + 1];
    const uint4* XH = (const uint4*)xh;
    float a[8];
#pragma unroll
    for (int j = 0; j < 8; j++) a[j] = 0.f;

    auto accum = [&](uint4 u) {
        float2 p;
        p = unpack_h2(u.x); a[0] += p.x; a[1] += p.y;
        p = unpack_h2(u.y); a[2] += p.x; a[3] += p.y;
        p = unpack_h2(u.z); a[4] += p.x; a[5] += p.y;
        p = unpack_h2(u.w); a[6] += p.x; a[7] += p.y;
    };

    int i = beg;
    for (; i + 3 < end; i += 4) {
        int s0 = csr[i], s1 = csr[i+1], s2 = csr[i+2], s3 = csr[i+3];
        uint4 v0 = XH[(size_t)s0 * 64 + t];
        uint4 v1 = XH[(size_t)s1 * 64 + t];
        uint4 v2 = XH[(size_t)s2 * 64 + t];
        uint4 v3 = XH[(size_t)s3 * 64 + t];
        accum(v0); accum(v1); accum(v2); accum(v3);
    }
    for (; i < end; i++) {
        accum(XH[(size_t)csr[i] * 64 + t]);
    }

    float inv = 1.0f / (float)max(end - beg, 1);
    uint4 u;
    uint32_t* pu = (uint32_t*)&u;
#pragma unroll
    for (int j = 0; j < 4; j++)
        pu[j] = pack_h2(a[j*2+0] * inv, a[j*2+1] * inv);
    ((uint4*)ah)[(size_t)node * 64 + t] = u;
}

// ---------------------------------------------------------------------------
// mma.sync fp16 GEMM:
// C[M, Ntot] = A0 @ B0^T + A1 @ B1^T + bias   (each K half 512)
// Single fp16 product per tile (weights + activations fp16), fp32 accum.
// CTA tile 128x128, 8 warps (4m x 2n), warp tile 32x64.
// K-chunk 64 halves, 2-stage cp.async pipeline, one __syncthreads per chunk.
// SMEM row stride 144B (128B data + 16B pad): ldmatrix conflict-free.
// ---------------------------------------------------------------------------
template <bool FP16_RELU>
__global__ __launch_bounds__(256, 2)
void gemm_mma(const __half* __restrict__ A0, const __half* __restrict__ A1,
              const __half* __restrict__ B0, const __half* __restrict__ B1,
              const float* __restrict__ bias,
              float* __restrict__ Cf, __half* __restrict__ Ch,
              int M, int Ntot) {
    extern __shared__ char dsm[];
    constexpr int SROW  = 144;         // 64 halves = 128B data + 16B pad
    constexpr int PLANE = 128 * SROW;  // 18432 B
    constexpr int STAGE = 2 * PLANE;   // 36864 B: A, B
    constexpr int OFF_A = 0, OFF_B = PLANE;

    const int tid  = threadIdx.x;
    const int wid  = tid >> 5;
    const int lane = tid & 31;
    const int wm = wid >> 1;
    const int wn = wid & 1;
    const int mBase = blockIdx.y * 128;
    const int nBase = blockIdx.x * 128;
    const uint32_t smem = smem_to_u32(dsm);

    // ---- async loader for one K-chunk (64 halves = 128B/row) into stage s ----
    auto issue_chunk = [&](int ch, int s) {
        const bool half = (ch >= 8);
        const char* Ap = (const char*)(half ? A1 : A0);
        const char* Bp = (const char*)(half ? B1 : B0);
        const int k0b = (ch & 7) * 128;          // byte offset within 1024B row
        const uint32_t sb = smem + s * STAGE;
#pragma unroll
        for (int it = 0; it < 4; it++) {
            int c = tid + it * 256;              // 0..1023
            int row = c >> 3, q = c & 7;
            uint32_t soff = row * SROW + q * 16;
            int am = mBase + row;
            int asz = (am < M) ? 16 : 0;
            size_t ga = (size_t)(am < M ? am : 0) * 1024 + k0b + q * 16;
            CP_ASYNC16(sb + OFF_A + soff, Ap + ga, asz);
            size_t gb = (size_t)(nBase + row) * 1024 + k0b + q * 16;
            CP_ASYNC16(sb + OFF_B + soff, Bp + gb, 16);
        }
        CP_COMMIT();
    };

    float acc[2][8][4];
#pragma unroll
    for (int i = 0; i < 2; i++)
#pragma unroll
        for (int j = 0; j < 8; j++)
#pragma unroll
            for (int k = 0; k < 4; k++) acc[i][j][k] = 0.f;

    const int g = lane >> 3, r = lane & 7;

    issue_chunk(0, 0);
    for (int ch = 0; ch < 16; ch++) {
        const int s = ch & 1;
        CP_WAIT(0);
        __syncthreads();                 // stage s visible; stage s^1 free
        if (ch + 1 < 16) issue_chunk(ch + 1, s ^ 1);

        const uint32_t sA = smem + s * STAGE + OFF_A;
        const uint32_t sB = smem + s * STAGE + OFF_B;

#pragma unroll
        for (int ks = 0; ks < 4; ks++) {
            uint32_t ah[2][4];
#pragma unroll
            for (int mi = 0; mi < 2; mi++) {
                uint32_t arow = wm * 32 + mi * 16 + ((g & 1) << 3) + r;
                uint32_t aoff = arow * SROW + ks * 32 + (g >> 1) * 16;
                LDSM_X4(ah[mi][0], ah[mi][1], ah[mi][2], ah[mi][3], sA + aoff);
            }
#pragma unroll
            for (int j = 0; j < 4; j++) {
                uint32_t brow = wn * 64 + j * 16 + ((g >> 1) << 3) + r;
                uint32_t boff = brow * SROW + ks * 32 + (g & 1) * 16;
                uint32_t b0, b1, b2, b3;
                LDSM_X4(b0, b1, b2, b3, sB + boff);
                // 4 distinct accumulators -> no back-to-back RAW
                MMA_FP16(acc[0][j*2+0], ah[0], b0, b1);
                MMA_FP16(acc[0][j*2+1], ah[0], b2, b3);
                MMA_FP16(acc[1][j*2+0], ah[1], b0, b1);
                MMA_FP16(acc[1][j*2+1], ah[1], b2, b3);
            }
        }
    }

    // ---- Epilogue ----
    const int qrow = lane >> 2, qcol = lane & 3;
#pragma unroll
    for (int mi = 0; mi < 2; mi++) {
#pragma unroll
        for (int ni = 0; ni < 8; ni++) {
            int row0 = mBase + wm * 32 + mi * 16 + qrow;
            int col  = nBase + wn * 64 + ni * 8 + qcol * 2;
            float2 bb = *(const float2*)(bias + col);
#pragma unroll
            for (int h = 0; h < 2; h++) {
                int row = row0 + h * 8;
                if (row >= M) continue;
                float v0 = acc[mi][ni][h*2+0] + bb.x;
                float v1 = acc[mi][ni][h*2+1] + bb.y;
                if (FP16_RELU) {
                    v0 = fmaxf(v0, 0.f); v1 = fmaxf(v1, 0.f);
                    *(uint32_t*)(Ch + (size_t)row * Ntot + col) = pack_h2(v0, v1);
                } else {
                    float2 o; o.x = v0; o.y = v1;
                    *(float2*)(Cf + (size_t)row * Ntot + col) = o;
                }
            }
        }
    }
}

// ---------------------------------------------------------------------------
// In-place log_softmax over rows of 128, one warp per row.
// ---------------------------------------------------------------------------
__global__ void log_softmax128_kernel(float* __restrict__ out, int M) {
    int row  = blockIdx.x * (blockDim.x >> 5) + (threadIdx.x >> 5);
    int lane = threadIdx.x & 31;
    if (row >= M) return;
    float4* p = (float4*)(out + (size_t)row * DOUT);
    float4 v = p[lane];
    float mx = fmaxf(fmaxf(v.x, v.y), fmaxf(v.z, v.w));
#pragma unroll
    for (int o = 16; o; o >>= 1) mx = fmaxf(mx, __shfl_xor_sync(0xffffffffu, mx, o));
    float s = expf(v.x - mx) + expf(v.y - mx) + expf(v.z - mx) + expf(v.w - mx);
#pragma unroll
    for (int o = 16; o; o >>= 1) s += __shfl_xor_sync(0xffffffffu, s, o);
    float l = mx + logf(s);
    v.x -= l; v.y -= l; v.z -= l; v.w -= l;
    p[lane] = v;
}

// ---------------------------------------------------------------------------
extern "C" void kernel_launch(void* const* d_in, const int* in_sizes, int n_in,
                              void* d_out, int out_size) {
    const float* x   = (const float*)d_in[0];
    const int*   ei  = (const int*)  d_in[1];
    const float* W1l = (const float*)d_in[2];
    const float* b1  = (const float*)d_in[3];
    const float* W1r = (const float*)d_in[4];
    const float* W2l = (const float*)d_in[5];
    const float* b2  = (const float*)d_in[6];
    const float* W2r = (const float*)d_in[7];
    const float* W3l = (const float*)d_in[8];
    const float* b3  = (const float*)d_in[9];
    const float* W3r = (const float*)d_in[10];
    float* out = (float*)d_out;

    const int E = in_sizes[1] / 2;
    const int M = in_sizes[0] / DDIM;
    const int* src = ei;
    const int* dst = ei + E;

    __half *xh,*ah,*h1,*h2;
    __half *w1l,*w1r,*w2l,*w2r,*w3l,*w3r;
    int *deg,*rowptr,*cursor,*csr,*bsums;
    cudaGetSymbolAddress((void**)&xh, g_x);
    cudaGetSymbolAddress((void**)&ah, g_a);
    cudaGetSymbolAddress((void**)&h1, g_h1);
    cudaGetSymbolAddress((void**)&h2, g_h2);
    cudaGetSymbolAddress((void**)&w1l, g_w1l);
    cudaGetSymbolAddress((void**)&w1r, g_w1r);
    cudaGetSymbolAddress((void**)&w2l, g_w2l);
    cudaGetSymbolAddress((void**)&w2r, g_w2r);
    cudaGetSymbolAddress((void**)&w3l, g_w3l);
    cudaGetSymbolAddress((void**)&w3r, g_w3r);
    cudaGetSymbolAddress((void**)&deg,    g_deg);
    cudaGetSymbolAddress((void**)&rowptr, g_rowptr);
    cudaGetSymbolAddress((void**)&cursor, g_cursor);
    cudaGetSymbolAddress((void**)&csr,    g_csr);
    cudaGetSymbolAddress((void**)&bsums,  g_bsums);

    const int nblk = (M + SCAN_B - 1) / SCAN_B;

    const int SMEM_GEMM = 2 * 2 * 128 * 144;  // 73728 B -> 2 CTAs/SM
    cudaFuncSetAttribute(gemm_mma<true>,  cudaFuncAttributeMaxDynamicSharedMemorySize, SMEM_GEMM);
    cudaFuncSetAttribute(gemm_mma<false>, cudaFuncAttributeMaxDynamicSharedMemorySize, SMEM_GEMM);

    // ---- CSR build ----
    zero2_int_kernel<<<(M + 255) / 256, 256>>>(deg, cursor, M);
    deg_kernel<<<(E + 255) / 256, 256>>>(dst, deg, E);
    scan1_kernel<<<nblk, SCAN_B>>>(deg, rowptr, bsums, M);
    scan2_kernel<<<1, 1>>>(bsums, rowptr, nblk, M);
    scan3_kernel<<<(M + 255) / 256, 256>>>(rowptr, bsums, M);
    csr_fill_kernel<<<(E + 255) / 256, 256>>>(src, dst, rowptr, cursor, csr, E);

    // ---- Conversions (single batched weight transpose + x conversion) ----
    convx_kernel<<<2048, 256>>>((const float4*)x, (uint2*)xh, M * DDIM / 4);
    wconv_all_kernel<<<dim3(16, 16, 6), dim3(32, 8)>>>(
        W1l, W1r, W2l, W2r, W3l, W3r, w1l, w1r, w2l, w2r, w3l, w3r);

    const int mTiles = (M + 127) / 128;
    const int gBlocks = (M + 3) / 4;

    // ---- Layer 1 ----
    gather_mean_kernel<<<gBlocks, 256>>>(xh, rowptr, csr, ah, M);
    gemm_mma<true><<<dim3(4, mTiles), 256, SMEM_GEMM>>>(
        ah, xh, w1l, w1r, b1, nullptr, h1, M, DDIM);

    // ---- Layer 2 ----
    gather_mean_kernel<<<gBlocks, 256>>>(h1, rowptr, csr, ah, M);
    gemm_mma<true><<<dim3(4, mTiles), 256, SMEM_GEMM>>>(
        ah, h1, w2l, w2r, b2, nullptr, h2, M, DDIM);

    // ---- Layer 3 ----
    gather_mean_kernel<<<gBlocks, 256>>>(h2, rowptr, csr, ah, M);
    gemm_mma<false><<<dim3(1, mTiles), 256, SMEM_GEMM>>>(
        ah, h2, w3l, w3r, b3, out, nullptr, M, DOUT);

    // log_softmax in place on d_out
    log_softmax128_kernel<<<(M + 7) / 8, 256>>>(out, M);
    (void)n_in; (void)out_size;
}

// round 11
// speedup vs baseline: 9.3711x; 1.0087x over previous
#include <cuda_runtime.h>
#include <cuda_fp16.h>
#include <cstdint>
#include <cstddef>

#define NN   50000
#define EE   400000
#define DDIM 512
#define DOUT 128
#define SCAN_B 512

// ---------------------------------------------------------------------------
// Scratch (device globals: allocation-free rule)
__device__ __half g_x  [(size_t)NN * DDIM];
__device__ __half g_a  [(size_t)NN * DDIM];
__device__ __half g_h1 [(size_t)NN * DDIM];
__device__ __half g_h2 [(size_t)NN * DDIM];
// Transposed weights [N][K] fp16
__device__ __half g_w1l[512*512];
__device__ __half g_w1r[512*512];
__device__ __half g_w2l[512*512];
__device__ __half g_w2r[512*512];
__device__ __half g_w3l[128*512];
__device__ __half g_w3r[128*512];
// CSR
__device__ int g_deg[NN];
__device__ int g_rowptr[NN + 1];
__device__ int g_cursor[NN];
__device__ int g_csr[EE];
__device__ int g_bsums[(NN + SCAN_B - 1) / SCAN_B + 1];

// ---------------------------------------------------------------------------
// PTX helpers (base-arch only: ldmatrix / mma.sync / cp.async)
// ---------------------------------------------------------------------------
__device__ __forceinline__ uint32_t smem_to_u32(const void* p) {
    uint32_t a;
    asm("{ .reg .u64 t; cvta.to.shared.u64 t, %1; cvt.u32.u64 %0, t; }"
        : "=r"(a) : "l"(p));
    return a;
}

#define LDSM_X4(r0, r1, r2, r3, addr) \
    asm volatile("ldmatrix.sync.aligned.m8n8.x4.shared.b16 {%0,%1,%2,%3}, [%4];" \
        : "=r"(r0), "=r"(r1), "=r"(r2), "=r"(r3) : "r"(addr))

#define MMA_FP16(c, a, bv0, bv1) \
    asm volatile("mma.sync.aligned.m16n8k16.row.col.f32.f16.f16.f32 " \
        "{%0,%1,%2,%3}, {%4,%5,%6,%7}, {%8,%9}, {%0,%1,%2,%3};" \
        : "+f"((c)[0]), "+f"((c)[1]), "+f"((c)[2]), "+f"((c)[3]) \
        : "r"((a)[0]), "r"((a)[1]), "r"((a)[2]), "r"((a)[3]), "r"(bv0), "r"(bv1))

#define CP_ASYNC16(smem, gmem, sz) \
    asm volatile("cp.async.cg.shared.global [%0], [%1], 16, %2;" \
        :: "r"(smem), "l"(gmem), "r"(sz) : "memory")
#define CP_COMMIT() asm volatile("cp.async.commit_group;" ::: "memory")
#define CP_WAIT(n)  asm volatile("cp.async.wait_group %0;" :: "n"(n) : "memory")

// ---------------------------------------------------------------------------
// fp16 helpers
// ---------------------------------------------------------------------------
__device__ __forceinline__ uint32_t pack_h2(float a, float b) {
    __half2 t = __floats2half2_rn(a, b);
    return *reinterpret_cast<uint32_t*>(&t);
}
__device__ __forceinline__ float2 unpack_h2(uint32_t u) {
    __half2 t = *reinterpret_cast<__half2*>(&u);
    return __half22float2(t);
}

// ---------------------------------------------------------------------------
// Fused pre-work kernel: block-range dispatch.
//   [0, ZEROB)                : zero deg + cursor
//   [ZEROB, ZEROB+CONVB)      : convx  (fp32 x -> fp16 plane, grid-stride)
//   [ZEROB+CONVB, +WCONVB)    : wconv  (transpose all 6 weights to fp16 [N][K])
// ---------------------------------------------------------------------------
#define ZEROB  196
#define CONVB  2048
#define WCONVB 1152   // 4*256 (512x512) + 2*64 (512x128)

__global__ void prep_kernel(const float4* __restrict__ x, uint2* __restrict__ xh,
                            int n4, int* __restrict__ deg, int* __restrict__ cursor, int M,
                            const float* __restrict__ W1l, const float* __restrict__ W1r,
                            const float* __restrict__ W2l, const float* __restrict__ W2r,
                            const float* __restrict__ W3l, const float* __restrict__ W3r,
                            __half* __restrict__ o1l, __half* __restrict__ o1r,
                            __half* __restrict__ o2l, __half* __restrict__ o2r,
                            __half* __restrict__ o3l, __half* __restrict__ o3r) {
    __shared__ float t[32][33];
    const int b = blockIdx.x;
    const int tid = threadIdx.x;
    if (b < ZEROB) {
        int i = b * 256 + tid;
        if (i < M) { deg[i] = 0; cursor[i] = 0; }
    } else if (b < ZEROB + CONVB) {
        int i = (b - ZEROB) * 256 + tid;
        const int stride = CONVB * 256;
        for (; i < n4; i += stride) {
            float4 v = x[i];
            uint2 u;
            u.x = pack_h2(v.x, v.y);
            u.y = pack_h2(v.z, v.w);
            xh[i] = u;
        }
    } else {
        int wb = b - ZEROB - CONVB;
        const float* W; __half* O; int N, idx;
        if (wb < 1024) {
            int z = wb >> 8; idx = wb & 255; N = 512;
            W = (z == 0) ? W1l : (z == 1) ? W1r : (z == 2) ? W2l : W2r;
            O = (z == 0) ? o1l : (z == 1) ? o1r : (z == 2) ? o2l : o2r;
        } else {
            int wb2 = wb - 1024; int z = wb2 >> 6; idx = wb2 & 63; N = 128;
            W = z ? W3r : W3l;
            O = z ? o3r : o3l;
        }
        const int nXb = N >> 5;                    // 16 or 4 col-blocks
        int nb = (idx % nXb) * 32, kb = (idx / nXb) * 32;
        int tx = tid & 31, ty = tid >> 5;
        for (int i = ty; i < 32; i += 8)
            t[i][tx] = W[(size_t)(kb + i) * N + nb + tx];
        __syncthreads();
        for (int i = ty; i < 32; i += 8) {
            float v = t[tx][i];
            O[(size_t)(nb + i) * 512 + kb + tx] = __float2half_rn(v);
        }
    }
}

// ---------------------------------------------------------------------------
// CSR construction
// ---------------------------------------------------------------------------
__global__ void deg_kernel(const int* __restrict__ dst, int* __restrict__ deg, int E) {
    int e = blockIdx.x * blockDim.x + threadIdx.x;
    if (e < E) atomicAdd(&deg[dst[e]], 1);
}
__global__ void scan1_kernel(const int* __restrict__ deg, int* __restrict__ rowptr,
                             int* __restrict__ bsums, int M) {
    __shared__ int sh[SCAN_B];
    int tid = threadIdx.x;
    int i = blockIdx.x * SCAN_B + tid;
    int v = (i < M) ? deg[i] : 0;
    sh[tid] = v;
    __syncthreads();
#pragma unroll
    for (int off = 1; off < SCAN_B; off <<= 1) {
        int t = (tid >= off) ? sh[tid - off] : 0;
        __syncthreads();
        sh[tid] += t;
        __syncthreads();
    }
    if (i < M) rowptr[i] = sh[tid] - v;
    if (tid == SCAN_B - 1) bsums[blockIdx.x] = sh[tid];
}
// scan3 with inline chunk-offset (scan2 eliminated): each thread sums the
// bsums prefix for its chunk (<=98 L1-hit loads); thread 0 writes rowptr[M].
__global__ void scan3_kernel(int* __restrict__ rowptr, const int* __restrict__ bsums,
                             int nblk, int M) {
    int i = blockIdx.x * blockDim.x + threadIdx.x;
    if (i < M) {
        int chunk = i / SCAN_B;
        int off = 0;
        for (int j = 0; j < chunk; j++) off += bsums[j];
        rowptr[i] += off;
    }
    if (i == 0) {
        int tot = 0;
        for (int j = 0; j < nblk; j++) tot += bsums[j];
        rowptr[M] = tot;
    }
}
__global__ void csr_fill_kernel(const int* __restrict__ src, const int* __restrict__ dst,
                                const int* __restrict__ rowptr, int* __restrict__ cursor,
                                int* __restrict__ csr, int E) {
    int e = blockIdx.x * blockDim.x + threadIdx.x;
    if (e < E) {
        int d = dst[e];
        int pos = atomicAdd(&cursor[d], 1);
        csr[rowptr[d] + pos] = src[e];
    }
}

// ---------------------------------------------------------------------------
// Gather-mean on fp16: 4 nodes per block, 64 threads per node,
// one uint4 (8 halves) per thread; 8-deep unroll for MLP=8.
// ---------------------------------------------------------------------------
__global__ void gather_mean_kernel(const __half* __restrict__ xh,
                                   const int* __restrict__ rowptr,
                                   const int* __restrict__ csr,
                                   __half* __restrict__ ah, int M) {
    int node = blockIdx.x * 4 + (threadIdx.x >> 6);
    int t    = threadIdx.x & 63;
    if (node >= M) return;
    int beg = rowptr[node], end = rowptr[node + 1];
    const uint4* XH = (const uint4*)xh;
    float a[8];
#pragma unroll
    for (int j = 0; j < 8; j++) a[j] = 0.f;

    auto accum = [&](uint4 u) {
        float2 p;
        p = unpack_h2(u.x); a[0] += p.x; a[1] += p.y;
        p = unpack_h2(u.y); a[2] += p.x; a[3] += p.y;
        p = unpack_h2(u.z); a[4] += p.x; a[5] += p.y;
        p = unpack_h2(u.w); a[6] += p.x; a[7] += p.y;
    };

    int i = beg;
    for (; i + 7 < end; i += 8) {
        uint4 v0 = XH[(size_t)csr[i+0] * 64 + t];
        uint4 v1 = XH[(size_t)csr[i+1] * 64 + t];
        uint4 v2 = XH[(size_t)csr[i+2] * 64 + t];
        uint4 v3 = XH[(size_t)csr[i+3] * 64 + t];
        uint4 v4 = XH[(size_t)csr[i+4] * 64 + t];
        uint4 v5 = XH[(size_t)csr[i+5] * 64 + t];
        uint4 v6 = XH[(size_t)csr[i+6] * 64 + t];
        uint4 v7 = XH[(size_t)csr[i+7] * 64 + t];
        accum(v0); accum(v1); accum(v2); accum(v3);
        accum(v4); accum(v5); accum(v6); accum(v7);
    }
    for (; i + 3 < end; i += 4) {
        uint4 v0 = XH[(size_t)csr[i+0] * 64 + t];
        uint4 v1 = XH[(size_t)csr[i+1] * 64 + t];
        uint4 v2 = XH[(size_t)csr[i+2] * 64 + t];
        uint4 v3 = XH[(size_t)csr[i+3] * 64 + t];
        accum(v0); accum(v1); accum(v2); accum(v3);
    }
    for (; i < end; i++) {
        accum(XH[(size_t)csr[i] * 64 + t]);
    }

    float inv = 1.0f / (float)max(end - beg, 1);
    uint4 u;
    uint32_t* pu = (uint32_t*)&u;
#pragma unroll
    for (int j = 0; j < 4; j++)
        pu[j] = pack_h2(a[j*2+0] * inv, a[j*2+1] * inv);
    ((uint4*)ah)[(size_t)node * 64 + t] = u;
}

// ---------------------------------------------------------------------------
// mma.sync fp16 GEMM:
// C[M, Ntot] = A0 @ B0^T + A1 @ B1^T + bias   (each K half 512)
// Single fp16 product, fp32 accum. CTA tile 128x128, 8 warps (4m x 2n).
// K-chunk 64 halves, 2-stage cp.async pipeline, one __syncthreads per chunk.
// SMEM row stride 144B (128B data + 16B pad): ldmatrix conflict-free.
// ---------------------------------------------------------------------------
template <bool FP16_RELU>
__global__ __launch_bounds__(256, 2)
void gemm_mma(const __half* __restrict__ A0, const __half* __restrict__ A1,
              const __half* __restrict__ B0, const __half* __restrict__ B1,
              const float* __restrict__ bias,
              float* __restrict__ Cf, __half* __restrict__ Ch,
              int M, int Ntot) {
    extern __shared__ char dsm[];
    constexpr int SROW  = 144;
    constexpr int PLANE = 128 * SROW;  // 18432 B
    constexpr int STAGE = 2 * PLANE;   // 36864 B: A, B
    constexpr int OFF_A = 0, OFF_B = PLANE;

    const int tid  = threadIdx.x;
    const int wid  = tid >> 5;
    const int lane = tid & 31;
    const int wm = wid >> 1;
    const int wn = wid & 1;
    const int mBase = blockIdx.y * 128;
    const int nBase = blockIdx.x * 128;
    const uint32_t smem = smem_to_u32(dsm);

    auto issue_chunk = [&](int ch, int s) {
        const bool half = (ch >= 8);
        const char* Ap = (const char*)(half ? A1 : A0);
        const char* Bp = (const char*)(half ? B1 : B0);
        const int k0b = (ch & 7) * 128;
        const uint32_t sb = smem + s * STAGE;
#pragma unroll
        for (int it = 0; it < 4; it++) {
            int c = tid + it * 256;
            int row = c >> 3, q = c & 7;
            uint32_t soff = row * SROW + q * 16;
            int am = mBase + row;
            int asz = (am < M) ? 16 : 0;
            size_t ga = (size_t)(am < M ? am : 0) * 1024 + k0b + q * 16;
            CP_ASYNC16(sb + OFF_A + soff, Ap + ga, asz);
            size_t gb = (size_t)(nBase + row) * 1024 + k0b + q * 16;
            CP_ASYNC16(sb + OFF_B + soff, Bp + gb, 16);
        }
        CP_COMMIT();
    };

    float acc[2][8][4];
#pragma unroll
    for (int i = 0; i < 2; i++)
#pragma unroll
        for (int j = 0; j < 8; j++)
#pragma unroll
            for (int k = 0; k < 4; k++) acc[i][j][k] = 0.f;

    const int g = lane >> 3, r = lane & 7;

    issue_chunk(0, 0);
    for (int ch = 0; ch < 16; ch++) {
        const int s = ch & 1;
        CP_WAIT(0);
        __syncthreads();
        if (ch + 1 < 16) issue_chunk(ch + 1, s ^ 1);

        const uint32_t sA = smem + s * STAGE + OFF_A;
        const uint32_t sB = smem + s * STAGE + OFF_B;

#pragma unroll
        for (int ks = 0; ks < 4; ks++) {
            uint32_t ah[2][4];
#pragma unroll
            for (int mi = 0; mi < 2; mi++) {
                uint32_t arow = wm * 32 + mi * 16 + ((g & 1) << 3) + r;
                uint32_t aoff = arow * SROW + ks * 32 + (g >> 1) * 16;
                LDSM_X4(ah[mi][0], ah[mi][1], ah[mi][2], ah[mi][3], sA + aoff);
            }
#pragma unroll
            for (int j = 0; j < 4; j++) {
                uint32_t brow = wn * 64 + j * 16 + ((g >> 1) << 3) + r;
                uint32_t boff = brow * SROW + ks * 32 + (g & 1) * 16;
                uint32_t b0, b1, b2, b3;
                LDSM_X4(b0, b1, b2, b3, sB + boff);
                MMA_FP16(acc[0][j*2+0], ah[0], b0, b1);
                MMA_FP16(acc[0][j*2+1], ah[0], b2, b3);
                MMA_FP16(acc[1][j*2+0], ah[1], b0, b1);
                MMA_FP16(acc[1][j*2+1], ah[1], b2, b3);
            }
        }
    }

    // ---- Epilogue ----
    const int qrow = lane >> 2, qcol = lane & 3;
#pragma unroll
    for (int mi = 0; mi < 2; mi++) {
#pragma unroll
        for (int ni = 0; ni < 8; ni++) {
            int row0 = mBase + wm * 32 + mi * 16 + qrow;
            int col  = nBase + wn * 64 + ni * 8 + qcol * 2;
            float2 bb = *(const float2*)(bias + col);
#pragma unroll
            for (int h = 0; h < 2; h++) {
                int row = row0 + h * 8;
                if (row >= M) continue;
                float v0 = acc[mi][ni][h*2+0] + bb.x;
                float v1 = acc[mi][ni][h*2+1] + bb.y;
                if (FP16_RELU) {
                    v0 = fmaxf(v0, 0.f); v1 = fmaxf(v1, 0.f);
                    *(uint32_t*)(Ch + (size_t)row * Ntot + col) = pack_h2(v0, v1);
                } else {
                    float2 o; o.x = v0; o.y = v1;
                    *(float2*)(Cf + (size_t)row * Ntot + col) = o;
                }
            }
        }
    }
}

// ---------------------------------------------------------------------------
// In-place log_softmax over rows of 128, one warp per row.
// ---------------------------------------------------------------------------
__global__ void log_softmax128_kernel(float* __restrict__ out, int M) {
    int row  = blockIdx.x * (blockDim.x >> 5) + (threadIdx.x >> 5);
    int lane = threadIdx.x & 31;
    if (row >= M) return;
    float4* p = (float4*)(out + (size_t)row * DOUT);
    float4 v = p[lane];
    float mx = fmaxf(fmaxf(v.x, v.y), fmaxf(v.z, v.w));
#pragma unroll
    for (int o = 16; o; o >>= 1) mx = fmaxf(mx, __shfl_xor_sync(0xffffffffu, mx, o));
    float s = expf(v.x - mx) + expf(v.y - mx) + expf(v.z - mx) + expf(v.w - mx);
#pragma unroll
    for (int o = 16; o; o >>= 1) s += __shfl_xor_sync(0xffffffffu, s, o);
    float l = mx + logf(s);
    v.x -= l; v.y -= l; v.z -= l; v.w -= l;
    p[lane] = v;
}

// ---------------------------------------------------------------------------
extern "C" void kernel_launch(void* const* d_in, const int* in_sizes, int n_in,
                              void* d_out, int out_size) {
    const float* x   = (const float*)d_in[0];
    const int*   ei  = (const int*)  d_in[1];
    const float* W1l = (const float*)d_in[2];
    const float* b1  = (const float*)d_in[3];
    const float* W1r = (const float*)d_in[4];
    const float* W2l = (const float*)d_in[5];
    const float* b2  = (const float*)d_in[6];
    const float* W2r = (const float*)d_in[7];
    const float* W3l = (const float*)d_in[8];
    const float* b3  = (const float*)d_in[9];
    const float* W3r = (const float*)d_in[10];
    float* out = (float*)d_out;

    const int E = in_sizes[1] / 2;
    const int M = in_sizes[0] / DDIM;
    const int* src = ei;
    const int* dst = ei + E;

    __half *xh,*ah,*h1,*h2;
    __half *w1l,*w1r,*w2l,*w2r,*w3l,*w3r;
    int *deg,*rowptr,*cursor,*csr,*bsums;
    cudaGetSymbolAddress((void**)&xh, g_x);
    cudaGetSymbolAddress((void**)&ah, g_a);
    cudaGetSymbolAddress((void**)&h1, g_h1);
    cudaGetSymbolAddress((void**)&h2, g_h2);
    cudaGetSymbolAddress((void**)&w1l, g_w1l);
    cudaGetSymbolAddress((void**)&w1r, g_w1r);
    cudaGetSymbolAddress((void**)&w2l, g_w2l);
    cudaGetSymbolAddress((void**)&w2r, g_w2r);
    cudaGetSymbolAddress((void**)&w3l, g_w3l);
    cudaGetSymbolAddress((void**)&w3r, g_w3r);
    cudaGetSymbolAddress((void**)&deg,    g_deg);
    cudaGetSymbolAddress((void**)&rowptr, g_rowptr);
    cudaGetSymbolAddress((void**)&cursor, g_cursor);
    cudaGetSymbolAddress((void**)&csr,    g_csr);
    cudaGetSymbolAddress((void**)&bsums,  g_bsums);

    const int nblk = (M + SCAN_B - 1) / SCAN_B;

    const int SMEM_GEMM = 2 * 2 * 128 * 144;  // 73728 B -> 2 CTAs/SM
    cudaFuncSetAttribute(gemm_mma<true>,  cudaFuncAttributeMaxDynamicSharedMemorySize, SMEM_GEMM);
    cudaFuncSetAttribute(gemm_mma<false>, cudaFuncAttributeMaxDynamicSharedMemorySize, SMEM_GEMM);

    // ---- Fused pre-work: zero + convx + all weight transposes (one launch) ----
    prep_kernel<<<ZEROB + CONVB + WCONVB, 256>>>(
        (const float4*)x, (uint2*)xh, M * DDIM / 4, deg, cursor, M,
        W1l, W1r, W2l, W2r, W3l, W3r, w1l, w1r, w2l, w2r, w3l, w3r);

    // ---- CSR build (scan2 folded into scan3) ----
    deg_kernel<<<(E + 255) / 256, 256>>>(dst, deg, E);
    scan1_kernel<<<nblk, SCAN_B>>>(deg, rowptr, bsums, M);
    scan3_kernel<<<(M + 255) / 256, 256>>>(rowptr, bsums, nblk, M);
    csr_fill_kernel<<<(E + 255) / 256, 256>>>(src, dst, rowptr, cursor, csr, E);

    const int mTiles = (M + 127) / 128;
    const int gBlocks = (M + 3) / 4;

    // ---- Layer 1 ----
    gather_mean_kernel<<<gBlocks, 256>>>(xh, rowptr, csr, ah, M);
    gemm_mma<true><<<dim3(4, mTiles), 256, SMEM_GEMM>>>(
        ah, xh, w1l, w1r, b1, nullptr, h1, M, DDIM);

    // ---- Layer 2 ----
    gather_mean_kernel<<<gBlocks, 256>>>(h1, rowptr, csr, ah, M);
    gemm_mma<true><<<dim3(4, mTiles), 256, SMEM_GEMM>>>(
        ah, h1, w2l, w2r, b2, nullptr, h2, M, DDIM);

    // ---- Layer 3 ----
    gather_mean_kernel<<<gBlocks, 256>>>(h2, rowptr, csr, ah, M);
    gemm_mma<false><<<dim3(1, mTiles), 256, SMEM_GEMM>>>(
        ah, h2, w3l, w3r, b3, out, nullptr, M, DOUT);

    // log_softmax in place on d_out
    log_softmax128_kernel<<<(M + 7) / 8, 256>>>(out, M);
    (void)n_in; (void)out_size;
}